// round 3
// baseline (speedup 1.0000x reference)
#include <cuda_runtime.h>
#include <cstdint>

#define N_NODES 50000
#define N_EDGES 800000
#define F_IN    128
#define HID     64
#define HEADS   4
#define L1_OUT  (HEADS*HID)   // 256
#define CLASSES 40
#define NEG_SLOPE 0.2f
#define EPS 1e-16f

#define GEMM1_UNITS 782            // (50000/128 rounded up = 391 row tiles) * 2 col tiles
#define HIST_BLOCKS 782            // 200000 threads * 4 edges
#define SCAN_BLOCKS 196            // ceil(50000/256)
#define SCAT_BLOCKS 782

// gemm1 unit split across the 5 fused kernels (sums to 782)
#define GA 350
#define GB 150
#define GC 50
#define GD 100
#define GE 132

// ---------------- scratch --------------------------------------------------
__device__ __align__(16) float g_h1  [(size_t)N_NODES * L1_OUT];
__device__ __align__(16) float g_out1[(size_t)N_NODES * L1_OUT];
__device__ __align__(16) float g_h2  [(size_t)N_NODES * CLASSES];
__device__ __align__(16) float g_as1[N_NODES * HEADS];
__device__ __align__(16) float g_ad1[N_NODES * HEADS];
__device__ float g_as2[N_NODES];
__device__ float g_ad2[N_NODES];
__device__ int   g_cnt[N_NODES];
__device__ int   g_start[N_NODES];
__device__ int   g_cursor[N_NODES];
__device__ int   g_ssrc[N_EDGES];
__device__ int   g_idx_is64 = 1;   // only ever written to 0 (data-determined, replay-safe)
__device__ int   g_bsum[SCAN_BLOCKS];
__device__ int   g_boff[SCAN_BLOCKS];

// ---------------- helpers ---------------------------------------------------
__device__ __forceinline__ float warpMax(float v) {
#pragma unroll
    for (int s = 16; s > 0; s >>= 1)
        v = fmaxf(v, __shfl_xor_sync(0xffffffffu, v, s));
    return v;
}
__device__ __forceinline__ float warpSum(float v) {
#pragma unroll
    for (int s = 16; s > 0; s >>= 1)
        v += __shfl_xor_sync(0xffffffffu, v, s);
    return v;
}
__device__ __forceinline__ float lrelu(float x) {
    return (x > 0.f) ? x : NEG_SLOPE * x;
}

// ---------------- prep: zero hist + int64/int32 detection --------------------
__global__ void prep_kernel(const long long* __restrict__ ei) {
    int i = blockIdx.x * blockDim.x + threadIdx.x;
    if (i < N_NODES) g_cnt[i] = 0;
    if (i < N_EDGES) {
        long long v = ei[i];
        if (v < 0 || v >= N_NODES) g_idx_is64 = 0;
    }
}

// ---------------- device-side pipeline stages --------------------------------
__device__ __forceinline__ void hist_block(int b, const void* __restrict__ eiv) {
    int e0 = (b * 256 + threadIdx.x) * 4;
    if (e0 >= N_EDGES) return;
    int d0, d1, d2, d3;
    if (g_idx_is64) {
        const longlong2* p = (const longlong2*)((const long long*)eiv + N_EDGES + e0);
        longlong2 a = __ldg(p), c = __ldg(p + 1);
        d0 = (int)a.x; d1 = (int)a.y; d2 = (int)c.x; d3 = (int)c.y;
    } else {
        int4 a = __ldg((const int4*)((const int*)eiv + N_EDGES + e0));
        d0 = a.x; d1 = a.y; d2 = a.z; d3 = a.w;
    }
    atomicAdd(&g_cnt[d0], 1);
    atomicAdd(&g_cnt[d1], 1);
    atomicAdd(&g_cnt[d2], 1);
    atomicAdd(&g_cnt[d3], 1);
}

__device__ __forceinline__ void scan1_block(int b, int* sh) {
    // sh: 2*256 ints
    int tid = threadIdx.x;
    int i = b * 256 + tid;
    int v = (i < N_NODES) ? g_cnt[i] : 0;
    sh[tid] = v;
    __syncthreads();
    int cur = 0;
#pragma unroll
    for (int s = 1; s < 256; s <<= 1) {
        int nxt = cur ^ 1;
        int t = sh[cur * 256 + tid];
        if (tid >= s) t += sh[cur * 256 + tid - s];
        sh[nxt * 256 + tid] = t;
        cur = nxt;
        __syncthreads();
    }
    int incl = sh[cur * 256 + tid];
    if (i < N_NODES) g_start[i] = incl - v;
    if (tid == 255) g_bsum[b] = incl;
}

__device__ __forceinline__ void scan2_block(int* sh) {
    int tid = threadIdx.x;
    int v = (tid < SCAN_BLOCKS) ? g_bsum[tid] : 0;
    sh[tid] = v;
    __syncthreads();
    int cur = 0;
#pragma unroll
    for (int s = 1; s < 256; s <<= 1) {
        int nxt = cur ^ 1;
        int t = sh[cur * 256 + tid];
        if (tid >= s) t += sh[cur * 256 + tid - s];
        sh[nxt * 256 + tid] = t;
        cur = nxt;
        __syncthreads();
    }
    if (tid < SCAN_BLOCKS) g_boff[tid] = sh[cur * 256 + tid] - v;
}

__device__ __forceinline__ void scan3_block(int b) {
    int i = b * 256 + threadIdx.x;
    if (i < N_NODES) {
        int st = g_start[i] + g_boff[b];
        g_start[i]  = st;
        g_cursor[i] = st;
    }
}

__device__ __forceinline__ void scatter_block(int b, const void* __restrict__ eiv) {
    int e0 = (b * 256 + threadIdx.x) * 4;
    if (e0 >= N_EDGES) return;
    int s0, s1, s2, s3, d0, d1, d2, d3;
    if (g_idx_is64) {
        const longlong2* ps = (const longlong2*)((const long long*)eiv + e0);
        const longlong2* pd = (const longlong2*)((const long long*)eiv + N_EDGES + e0);
        longlong2 a = __ldg(ps), c = __ldg(ps + 1);
        longlong2 e = __ldg(pd), f = __ldg(pd + 1);
        s0 = (int)a.x; s1 = (int)a.y; s2 = (int)c.x; s3 = (int)c.y;
        d0 = (int)e.x; d1 = (int)e.y; d2 = (int)f.x; d3 = (int)f.y;
    } else {
        int4 a = __ldg((const int4*)((const int*)eiv + e0));
        int4 e = __ldg((const int4*)((const int*)eiv + N_EDGES + e0));
        s0 = a.x; s1 = a.y; s2 = a.z; s3 = a.w;
        d0 = e.x; d1 = e.y; d2 = e.z; d3 = e.w;
    }
    g_ssrc[atomicAdd(&g_cursor[d0], 1)] = s0;
    g_ssrc[atomicAdd(&g_cursor[d1], 1)] = s1;
    g_ssrc[atomicAdd(&g_cursor[d2], 1)] = s2;
    g_ssrc[atomicAdd(&g_cursor[d3], 1)] = s3;
}

// ---------------- GEMM1 tile (128x128, BK=16, TM=TN=8) + fused alpha1 --------
__device__ __forceinline__ void gemm1_tile(
    int unit, float* sm,
    const float* __restrict__ A, const float* __restrict__ B,
    const float* __restrict__ a_src, const float* __restrict__ a_dst)
{
    float* As = sm;            // [16][128]
    float* Bs = sm + 2048;     // [16][128]
    int tid = threadIdx.x;
    int tr = tid >> 4, tc = tid & 15;
    int bn = (unit & 1) * 128;
    int bm = (unit >> 1) * 128;

    int arow = tid >> 1;
    int acol = (tid & 1) * 8;
    int brow = tid >> 4;
    int bcol = (tid & 15) * 8;

    const float* Aptr = A + (size_t)(bm + arow) * F_IN + acol;
    bool aval = (bm + arow) < N_NODES;
    const float* Bptr = B + (size_t)brow * L1_OUT + bn + bcol;

    float4 z = make_float4(0.f, 0.f, 0.f, 0.f);
    float4 ra0 = aval ? __ldg((const float4*)Aptr)       : z;
    float4 ra1 = aval ? __ldg((const float4*)(Aptr + 4)) : z;
    float4 rb0 = __ldg((const float4*)Bptr);
    float4 rb1 = __ldg((const float4*)(Bptr + 4));

    float acc[8][8] = {};

    for (int kk = 0; kk < F_IN / 16; kk++) {
        __syncthreads();
        As[(acol + 0) * 128 + arow] = ra0.x; As[(acol + 1) * 128 + arow] = ra0.y;
        As[(acol + 2) * 128 + arow] = ra0.z; As[(acol + 3) * 128 + arow] = ra0.w;
        As[(acol + 4) * 128 + arow] = ra1.x; As[(acol + 5) * 128 + arow] = ra1.y;
        As[(acol + 6) * 128 + arow] = ra1.z; As[(acol + 7) * 128 + arow] = ra1.w;
        *(float4*)&Bs[brow * 128 + bcol]     = rb0;
        *(float4*)&Bs[brow * 128 + bcol + 4] = rb1;
        __syncthreads();
        if (kk < F_IN / 16 - 1) {
            int k0 = (kk + 1) * 16;
            ra0 = aval ? __ldg((const float4*)(Aptr + k0))     : z;
            ra1 = aval ? __ldg((const float4*)(Aptr + k0 + 4)) : z;
            rb0 = __ldg((const float4*)(Bptr + (size_t)k0 * L1_OUT));
            rb1 = __ldg((const float4*)(Bptr + (size_t)k0 * L1_OUT + 4));
        }
#pragma unroll
        for (int k = 0; k < 16; k++) {
            float4 av0 = *(const float4*)&As[k * 128 + tr * 8];
            float4 av1 = *(const float4*)&As[k * 128 + tr * 8 + 4];
            float4 bv0 = *(const float4*)&Bs[k * 128 + tc * 8];
            float4 bv1 = *(const float4*)&Bs[k * 128 + tc * 8 + 4];
            float a[8] = {av0.x, av0.y, av0.z, av0.w, av1.x, av1.y, av1.z, av1.w};
            float b[8] = {bv0.x, bv0.y, bv0.z, bv0.w, bv1.x, bv1.y, bv1.z, bv1.w};
#pragma unroll
            for (int x = 0; x < 8; x++)
#pragma unroll
                for (int y = 0; y < 8; y++)
                    acc[x][y] = fmaf(a[x], b[y], acc[x][y]);
        }
    }

    int head = (bn >> 6) + (tc >> 3);
    int chbase = (tc & 7) * 8;
    float asv[8], adv[8];
#pragma unroll
    for (int y = 0; y < 8; y++) {
        asv[y] = __ldg(a_src + head * HID + chbase + y);
        adv[y] = __ldg(a_dst + head * HID + chbase + y);
    }
    float ps[8], pd[8];
#pragma unroll
    for (int x = 0; x < 8; x++) {
        float s = 0.f, d = 0.f;
#pragma unroll
        for (int y = 0; y < 8; y++) {
            s = fmaf(acc[x][y], asv[y], s);
            d = fmaf(acc[x][y], adv[y], d);
        }
        ps[x] = s; pd[x] = d;
    }
#pragma unroll
    for (int s = 1; s < 8; s <<= 1) {
#pragma unroll
        for (int x = 0; x < 8; x++) {
            ps[x] += __shfl_xor_sync(0xffffffffu, ps[x], s);
            pd[x] += __shfl_xor_sync(0xffffffffu, pd[x], s);
        }
    }
#pragma unroll
    for (int x = 0; x < 8; x++) {
        int r = bm + tr * 8 + x;
        if (r < N_NODES) {
            float* cp = g_h1 + (size_t)r * L1_OUT + bn + tc * 8;
            float4 o0 = {acc[x][0], acc[x][1], acc[x][2], acc[x][3]};
            float4 o1 = {acc[x][4], acc[x][5], acc[x][6], acc[x][7]};
            *(float4*)cp       = o0;
            *(float4*)(cp + 4) = o1;
            if ((tc & 7) == 0) {
                g_as1[r * 4 + head] = ps[x];
                g_ad1[r * 4 + head] = pd[x];
            }
        }
    }
}

// ---------------- fused kernels: gemm1 slice + one sort stage ----------------
__global__ __launch_bounds__(256) void kA(const float* __restrict__ x, const float* __restrict__ W1,
                                          const float* __restrict__ as, const float* __restrict__ ad,
                                          const void* __restrict__ ei) {
    extern __shared__ float sm[];
    if (blockIdx.x < GA) gemm1_tile(blockIdx.x, sm, x, W1, as, ad);
    else                 hist_block(blockIdx.x - GA, ei);
}
__global__ __launch_bounds__(256) void kB(const float* __restrict__ x, const float* __restrict__ W1,
                                          const float* __restrict__ as, const float* __restrict__ ad) {
    extern __shared__ float sm[];
    if (blockIdx.x < GB) gemm1_tile(GA + blockIdx.x, sm, x, W1, as, ad);
    else                 scan1_block(blockIdx.x - GB, (int*)sm);
}
__global__ __launch_bounds__(256) void kC(const float* __restrict__ x, const float* __restrict__ W1,
                                          const float* __restrict__ as, const float* __restrict__ ad) {
    extern __shared__ float sm[];
    if (blockIdx.x < GC) gemm1_tile(GA + GB + blockIdx.x, sm, x, W1, as, ad);
    else                 scan2_block((int*)sm);
}
__global__ __launch_bounds__(256) void kD(const float* __restrict__ x, const float* __restrict__ W1,
                                          const float* __restrict__ as, const float* __restrict__ ad) {
    extern __shared__ float sm[];
    if (blockIdx.x < GD) gemm1_tile(GA + GB + GC + blockIdx.x, sm, x, W1, as, ad);
    else                 scan3_block(blockIdx.x - GD);
}
__global__ __launch_bounds__(256) void kE(const float* __restrict__ x, const float* __restrict__ W1,
                                          const float* __restrict__ as, const float* __restrict__ ad,
                                          const void* __restrict__ ei) {
    extern __shared__ float sm[];
    if (blockIdx.x < GE) gemm1_tile(GA + GB + GC + GD + blockIdx.x, sm, x, W1, as, ad);
    else                 scatter_block(blockIdx.x - GE, ei);
}

// ---------------- layer-1 aggregation: chunked + shuffle broadcast ----------
__global__ __launch_bounds__(256) void agg1_kernel(const float* __restrict__ b1) {
    int n = (blockIdx.x * blockDim.x + threadIdx.x) >> 5;
    if (n >= N_NODES) return;
    int lane = threadIdx.x & 31;
    int head = lane >> 3;
    int s0 = g_start[n];
    int c  = g_cnt[n];
    float4 adv = *(const float4*)(g_ad1 + n * 4);

    float a0=0,a1=0,a2=0,a3=0,a4=0,a5=0,a6=0,a7=0, denom=0.f;

    for (int base = 0; base < c; base += 32) {
        int m = min(32, c - base);
        int sl = 0;
        float4 av = make_float4(0.f, 0.f, 0.f, 0.f);
        if (lane < m) {
            sl = __ldg(g_ssrc + s0 + base + lane);
            av = __ldg((const float4*)(g_as1 + sl * 4));
        }
        float x0 = __expf(lrelu(av.x + adv.x));
        float x1 = __expf(lrelu(av.y + adv.y));
        float x2 = __expf(lrelu(av.z + adv.z));
        float x3 = __expf(lrelu(av.w + adv.w));
#pragma unroll 4
        for (int j = 0; j < m; j++) {
            int   s  = __shfl_sync(0xffffffffu, sl, j);
            float y0 = __shfl_sync(0xffffffffu, x0, j);
            float y1 = __shfl_sync(0xffffffffu, x1, j);
            float y2 = __shfl_sync(0xffffffffu, x2, j);
            float y3 = __shfl_sync(0xffffffffu, x3, j);
            float xh = (head == 0) ? y0 : (head == 1) ? y1 : (head == 2) ? y2 : y3;
            const float4* hp = (const float4*)(g_h1 + (size_t)s * L1_OUT + (lane << 3));
            float4 v0 = __ldg(hp), v1 = __ldg(hp + 1);
            denom += xh;
            a0 = fmaf(xh, v0.x, a0); a1 = fmaf(xh, v0.y, a1);
            a2 = fmaf(xh, v0.z, a2); a3 = fmaf(xh, v0.w, a3);
            a4 = fmaf(xh, v1.x, a4); a5 = fmaf(xh, v1.y, a5);
            a6 = fmaf(xh, v1.z, a6); a7 = fmaf(xh, v1.w, a7);
        }
    }

    float inv = 1.0f / (denom + EPS);
    int col = lane * 8;
    float4 bA = *(const float4*)(b1 + col);
    float4 bB = *(const float4*)(b1 + col + 4);
    float4 oA, oB;
    oA.x = fmaxf(0.f, fmaf(a0, inv, bA.x));
    oA.y = fmaxf(0.f, fmaf(a1, inv, bA.y));
    oA.z = fmaxf(0.f, fmaf(a2, inv, bA.z));
    oA.w = fmaxf(0.f, fmaf(a3, inv, bA.w));
    oB.x = fmaxf(0.f, fmaf(a4, inv, bB.x));
    oB.y = fmaxf(0.f, fmaf(a5, inv, bB.y));
    oB.z = fmaxf(0.f, fmaf(a6, inv, bB.z));
    oB.w = fmaxf(0.f, fmaf(a7, inv, bB.w));
    *(float4*)(g_out1 + (size_t)n * L1_OUT + col)     = oA;
    *(float4*)(g_out1 + (size_t)n * L1_OUT + col + 4) = oB;
}

// ---------------- GEMM2 fused with alpha2 ------------------------------------
__global__ __launch_bounds__(256) void gemm2_kernel(
    const float* __restrict__ W2,
    const float* __restrict__ a_src, const float* __restrict__ a_dst)
{
    __shared__ float As[32][128];
    __shared__ float Bs[32][40];
    int tid = threadIdx.x;
    int tr = tid >> 3, tc = tid & 7;
    int bm = blockIdx.x * 128;

    int arow = tid >> 1;
    int acol = (tid & 1) * 16;
    const float* Aptr = g_out1 + (size_t)(bm + arow) * L1_OUT + acol;
    bool aval = (bm + arow) < N_NODES;
    int bidx = tid * 5;

    float4 sa[4];
    float  sb[5];
    float4 z = make_float4(0.f, 0.f, 0.f, 0.f);
#pragma unroll
    for (int q = 0; q < 4; q++)
        sa[q] = aval ? __ldg((const float4*)(Aptr + q * 4)) : z;
#pragma unroll
    for (int j = 0; j < 5; j++) sb[j] = __ldg(W2 + bidx + j);

    float acc[4][5] = {};

    for (int kk = 0; kk < L1_OUT / 32; kk++) {
        __syncthreads();
#pragma unroll
        for (int q = 0; q < 4; q++) {
            As[acol + q * 4 + 0][arow] = sa[q].x;
            As[acol + q * 4 + 1][arow] = sa[q].y;
            As[acol + q * 4 + 2][arow] = sa[q].z;
            As[acol + q * 4 + 3][arow] = sa[q].w;
        }
#pragma unroll
        for (int j = 0; j < 5; j++) ((float*)Bs)[bidx + j] = sb[j];
        __syncthreads();
        if (kk < L1_OUT / 32 - 1) {
            int k0 = (kk + 1) * 32;
#pragma unroll
            for (int q = 0; q < 4; q++)
                sa[q] = aval ? __ldg((const float4*)(Aptr + k0 + q * 4)) : z;
#pragma unroll
            for (int j = 0; j < 5; j++) sb[j] = __ldg(W2 + k0 * CLASSES + bidx + j);
        }
#pragma unroll
        for (int k = 0; k < 32; k++) {
            float4 av = *(const float4*)&As[k][tr * 4];
            float a[4] = {av.x, av.y, av.z, av.w};
            float b[5];
#pragma unroll
            for (int j = 0; j < 5; j++) b[j] = Bs[k][tc * 5 + j];
#pragma unroll
            for (int x = 0; x < 4; x++)
#pragma unroll
                for (int y = 0; y < 5; y++)
                    acc[x][y] = fmaf(a[x], b[y], acc[x][y]);
        }
    }

    float asv[5], adv[5];
#pragma unroll
    for (int y = 0; y < 5; y++) {
        asv[y] = __ldg(a_src + tc * 5 + y);
        adv[y] = __ldg(a_dst + tc * 5 + y);
    }
    float ps[4], pd[4];
#pragma unroll
    for (int x = 0; x < 4; x++) {
        float s = 0.f, d = 0.f;
#pragma unroll
        for (int y = 0; y < 5; y++) {
            s = fmaf(acc[x][y], asv[y], s);
            d = fmaf(acc[x][y], adv[y], d);
        }
        ps[x] = s; pd[x] = d;
    }
#pragma unroll
    for (int s = 1; s < 8; s <<= 1) {
#pragma unroll
        for (int x = 0; x < 4; x++) {
            ps[x] += __shfl_xor_sync(0xffffffffu, ps[x], s);
            pd[x] += __shfl_xor_sync(0xffffffffu, pd[x], s);
        }
    }
#pragma unroll
    for (int x = 0; x < 4; x++) {
        int r = bm + tr * 4 + x;
        if (r < N_NODES) {
            float* cp = g_h2 + (size_t)r * CLASSES + tc * 5;
#pragma unroll
            for (int y = 0; y < 5; y++) cp[y] = acc[x][y];
            if (tc == 0) {
                g_as2[r] = ps[x];
                g_ad2[r] = pd[x];
            }
        }
    }
}

// ---------------- layer-2 aggregation + fused log_softmax -------------------
__global__ __launch_bounds__(256) void agg2_kernel(const float* __restrict__ b2,
                                                   float* __restrict__ out) {
    int n = (blockIdx.x * blockDim.x + threadIdx.x) >> 5;
    if (n >= N_NODES) return;
    int lane = threadIdx.x & 31;
    bool hi = lane < 8;
    int s0 = g_start[n];
    int c  = g_cnt[n];
    float adn = __ldg(g_ad2 + n);

    float acc0 = 0.f, acc1 = 0.f, denom = 0.f;
    for (int base = 0; base < c; base += 32) {
        int m = min(32, c - base);
        int sl = 0;
        float e = 0.f;
        if (lane < m) {
            sl = __ldg(g_ssrc + s0 + base + lane);
            e  = __ldg(g_as2 + sl);
        }
        float xl = __expf(lrelu(e + adn));
#pragma unroll 4
        for (int j = 0; j < m; j++) {
            int   s = __shfl_sync(0xffffffffu, sl, j);
            float x = __shfl_sync(0xffffffffu, xl, j);
            const float* hp = g_h2 + (size_t)s * CLASSES;
            float h0 = __ldg(hp + lane);
            float h1 = hi ? __ldg(hp + 32 + lane) : 0.f;
            denom += x;
            acc0 = fmaf(x, h0, acc0);
            acc1 = fmaf(x, h1, acc1);
        }
    }
    float inv = 1.0f / (denom + EPS);
    float o0 = fmaf(acc0, inv, __ldg(b2 + lane));
    float o1 = hi ? fmaf(acc1, inv, __ldg(b2 + 32 + lane)) : -1e30f;

    float mx = warpMax(fmaxf(o0, o1));
    float se = __expf(o0 - mx) + (hi ? __expf(o1 - mx) : 0.f);
    se = warpSum(se);
    float ls = __logf(se);
    out[(size_t)n * CLASSES + lane] = o0 - mx - ls;
    if (hi) out[(size_t)n * CLASSES + 32 + lane] = o1 - mx - ls;
}

// ---------------- launch -----------------------------------------------------
extern "C" void kernel_launch(void* const* d_in, const int* in_sizes, int n_in,
                              void* d_out, int out_size) {
    const float* x    = (const float*)d_in[0];
    const void*  ei   = d_in[1];
    const float* W1   = (const float*)d_in[2];
    const float* asr1 = (const float*)d_in[3];
    const float* adt1 = (const float*)d_in[4];
    const float* b1   = (const float*)d_in[5];
    const float* W2   = (const float*)d_in[6];
    const float* asr2 = (const float*)d_in[7];
    const float* adt2 = (const float*)d_in[8];
    const float* b2   = (const float*)d_in[9];
    float* out = (float*)d_out;

    const int SMEM = 4096 * sizeof(float);   // 16 KB: gemm1 tiles / scan scratch

    prep_kernel<<<(N_EDGES + 255) / 256, 256>>>((const long long*)ei);

    kA<<<GA + HIST_BLOCKS, 256, SMEM>>>(x, W1, asr1, adt1, ei);
    kB<<<GB + SCAN_BLOCKS, 256, SMEM>>>(x, W1, asr1, adt1);
    kC<<<GC + 1,           256, SMEM>>>(x, W1, asr1, adt1);
    kD<<<GD + SCAN_BLOCKS, 256, SMEM>>>(x, W1, asr1, adt1);
    kE<<<GE + SCAT_BLOCKS, 256, SMEM>>>(x, W1, asr1, adt1, ei);

    agg1_kernel<<<(N_NODES + 7) / 8, 256>>>(b1);
    gemm2_kernel<<<(N_NODES + 127) / 128, 256>>>(W2, asr2, adt2);
    agg2_kernel<<<(N_NODES + 7) / 8, 256>>>(b2, out);
}

// round 4
// speedup vs baseline: 1.0994x; 1.0994x over previous
#include <cuda_runtime.h>
#include <cstdint>

#define N_NODES 50000
#define N_EDGES 800000
#define F_IN    128
#define HID     64
#define HEADS   4
#define L1_OUT  (HEADS*HID)   // 256
#define CLASSES 40
#define NEG_SLOPE 0.2f
#define EPS 1e-16f

#define GEMM1_UNITS 782            // 391 row tiles * 2 col tiles
#define EDGE_BLOCKS 782            // ceil(800000 / (256*4))
#define SCAN_BLOCKS 196            // ceil(50000/256)

// ---------------- scratch --------------------------------------------------
__device__ __align__(16) float g_h1  [(size_t)N_NODES * L1_OUT];
__device__ __align__(16) float g_out1[(size_t)N_NODES * L1_OUT];
__device__ __align__(16) float g_h2  [(size_t)N_NODES * CLASSES];
__device__ __align__(16) float g_as1[N_NODES * HEADS];
__device__ __align__(16) float g_ad1[N_NODES * HEADS];
__device__ float g_as2[N_NODES];
__device__ float g_ad2[N_NODES];
__device__ int   g_cnt[N_NODES];
__device__ int   g_start[N_NODES];
__device__ int   g_cursor[N_NODES];
__device__ int   g_ssrc[N_EDGES];
__device__ int   g_idx_is64;
__device__ int   g_bsum[SCAN_BLOCKS];
__device__ int   g_boff[SCAN_BLOCKS];

// ---------------- helpers ---------------------------------------------------
__device__ __forceinline__ float warpMax(float v) {
#pragma unroll
    for (int s = 16; s > 0; s >>= 1)
        v = fmaxf(v, __shfl_xor_sync(0xffffffffu, v, s));
    return v;
}
__device__ __forceinline__ float warpSum(float v) {
#pragma unroll
    for (int s = 16; s > 0; s >>= 1)
        v += __shfl_xor_sync(0xffffffffu, v, s);
    return v;
}
__device__ __forceinline__ float lrelu(float x) {
    return (x > 0.f) ? x : NEG_SLOPE * x;
}

// ---------------- prep ---------------------------------------------------
__global__ void zero_init_kernel() {
    int i = blockIdx.x * blockDim.x + threadIdx.x;
    if (i < N_NODES) g_cnt[i] = 0;
    if (i == 0) g_idx_is64 = 1;
}
__global__ void detect_kernel(const long long* __restrict__ ei) {
    int i = blockIdx.x * blockDim.x + threadIdx.x;
    if (i < N_EDGES) {
        long long v = ei[i];
        if (v < 0 || v >= N_NODES) g_idx_is64 = 0;
    }
}

// ---------------- GEMM1 tile (128x128, BK=16, TM=TN=8) + fused alpha1 --------
__device__ __forceinline__ void gemm1_tile(
    int unit, float* sm,
    const float* __restrict__ A, const float* __restrict__ B,
    const float* __restrict__ a_src, const float* __restrict__ a_dst)
{
    float* As = sm;            // [16][128]
    float* Bs = sm + 2048;     // [16][128]
    int tid = threadIdx.x;
    int tr = tid >> 4, tc = tid & 15;
    int bn = (unit & 1) * 128;
    int bm = (unit >> 1) * 128;

    int arow = tid >> 1;
    int acol = (tid & 1) * 8;
    int brow = tid >> 4;
    int bcol = (tid & 15) * 8;

    const float* Aptr = A + (size_t)(bm + arow) * F_IN + acol;
    bool aval = (bm + arow) < N_NODES;
    const float* Bptr = B + (size_t)brow * L1_OUT + bn + bcol;

    float4 z = make_float4(0.f, 0.f, 0.f, 0.f);
    float4 ra0 = aval ? __ldg((const float4*)Aptr)       : z;
    float4 ra1 = aval ? __ldg((const float4*)(Aptr + 4)) : z;
    float4 rb0 = __ldg((const float4*)Bptr);
    float4 rb1 = __ldg((const float4*)(Bptr + 4));

    float acc[8][8] = {};

    for (int kk = 0; kk < F_IN / 16; kk++) {
        __syncthreads();
        As[(acol + 0) * 128 + arow] = ra0.x; As[(acol + 1) * 128 + arow] = ra0.y;
        As[(acol + 2) * 128 + arow] = ra0.z; As[(acol + 3) * 128 + arow] = ra0.w;
        As[(acol + 4) * 128 + arow] = ra1.x; As[(acol + 5) * 128 + arow] = ra1.y;
        As[(acol + 6) * 128 + arow] = ra1.z; As[(acol + 7) * 128 + arow] = ra1.w;
        *(float4*)&Bs[brow * 128 + bcol]     = rb0;
        *(float4*)&Bs[brow * 128 + bcol + 4] = rb1;
        __syncthreads();
        if (kk < F_IN / 16 - 1) {
            int k0 = (kk + 1) * 16;
            ra0 = aval ? __ldg((const float4*)(Aptr + k0))     : z;
            ra1 = aval ? __ldg((const float4*)(Aptr + k0 + 4)) : z;
            rb0 = __ldg((const float4*)(Bptr + (size_t)k0 * L1_OUT));
            rb1 = __ldg((const float4*)(Bptr + (size_t)k0 * L1_OUT + 4));
        }
#pragma unroll
        for (int k = 0; k < 16; k++) {
            float4 av0 = *(const float4*)&As[k * 128 + tr * 8];
            float4 av1 = *(const float4*)&As[k * 128 + tr * 8 + 4];
            float4 bv0 = *(const float4*)&Bs[k * 128 + tc * 8];
            float4 bv1 = *(const float4*)&Bs[k * 128 + tc * 8 + 4];
            float a[8] = {av0.x, av0.y, av0.z, av0.w, av1.x, av1.y, av1.z, av1.w};
            float b[8] = {bv0.x, bv0.y, bv0.z, bv0.w, bv1.x, bv1.y, bv1.z, bv1.w};
#pragma unroll
            for (int x = 0; x < 8; x++)
#pragma unroll
                for (int y = 0; y < 8; y++)
                    acc[x][y] = fmaf(a[x], b[y], acc[x][y]);
        }
    }

    int head = (bn >> 6) + (tc >> 3);
    int chbase = (tc & 7) * 8;
    float asv[8], adv[8];
#pragma unroll
    for (int y = 0; y < 8; y++) {
        asv[y] = __ldg(a_src + head * HID + chbase + y);
        adv[y] = __ldg(a_dst + head * HID + chbase + y);
    }
    float ps[8], pd[8];
#pragma unroll
    for (int x = 0; x < 8; x++) {
        float s = 0.f, d = 0.f;
#pragma unroll
        for (int y = 0; y < 8; y++) {
            s = fmaf(acc[x][y], asv[y], s);
            d = fmaf(acc[x][y], adv[y], d);
        }
        ps[x] = s; pd[x] = d;
    }
#pragma unroll
    for (int s = 1; s < 8; s <<= 1) {
#pragma unroll
        for (int x = 0; x < 8; x++) {
            ps[x] += __shfl_xor_sync(0xffffffffu, ps[x], s);
            pd[x] += __shfl_xor_sync(0xffffffffu, pd[x], s);
        }
    }
#pragma unroll
    for (int x = 0; x < 8; x++) {
        int r = bm + tr * 8 + x;
        if (r < N_NODES) {
            float* cp = g_h1 + (size_t)r * L1_OUT + bn + tc * 8;
            float4 o0 = {acc[x][0], acc[x][1], acc[x][2], acc[x][3]};
            float4 o1 = {acc[x][4], acc[x][5], acc[x][6], acc[x][7]};
            *(float4*)cp       = o0;
            *(float4*)(cp + 4) = o1;
            if ((tc & 7) == 0) {
                g_as1[r * 4 + head] = ps[x];
                g_ad1[r * 4 + head] = pd[x];
            }
        }
    }
}

__device__ __forceinline__ void hist_block(int b, const void* __restrict__ eiv) {
    int e0 = (b * 256 + threadIdx.x) * 4;
    if (e0 >= N_EDGES) return;
    int d0, d1, d2, d3;
    if (g_idx_is64) {
        const longlong2* p = (const longlong2*)((const long long*)eiv + N_EDGES + e0);
        longlong2 a = __ldg(p), c = __ldg(p + 1);
        d0 = (int)a.x; d1 = (int)a.y; d2 = (int)c.x; d3 = (int)c.y;
    } else {
        int4 a = __ldg((const int4*)((const int*)eiv + N_EDGES + e0));
        d0 = a.x; d1 = a.y; d2 = a.z; d3 = a.w;
    }
    atomicAdd(&g_cnt[d0], 1);
    atomicAdd(&g_cnt[d1], 1);
    atomicAdd(&g_cnt[d2], 1);
    atomicAdd(&g_cnt[d3], 1);
}

// GEMM1 (all 782 tiles) + hist (independent) in ONE grid — no wave slicing.
__global__ __launch_bounds__(256) void kMain(
    const float* __restrict__ x, const float* __restrict__ W1,
    const float* __restrict__ as, const float* __restrict__ ad,
    const void* __restrict__ ei)
{
    __shared__ float sm[4096];
    if (blockIdx.x < GEMM1_UNITS) gemm1_tile(blockIdx.x, sm, x, W1, as, ad);
    else                          hist_block(blockIdx.x - GEMM1_UNITS, ei);
}

// ---------------- two-level scan ---------------------------------------------
__global__ void scan1_kernel() {
    __shared__ int sh[2][256];
    int tid = threadIdx.x;
    int i = blockIdx.x * 256 + tid;
    int v = (i < N_NODES) ? g_cnt[i] : 0;
    sh[0][tid] = v;
    __syncthreads();
    int cur = 0;
#pragma unroll
    for (int s = 1; s < 256; s <<= 1) {
        int nxt = cur ^ 1;
        int t = sh[cur][tid];
        if (tid >= s) t += sh[cur][tid - s];
        sh[nxt][tid] = t;
        cur = nxt;
        __syncthreads();
    }
    int incl = sh[cur][tid];
    if (i < N_NODES) g_start[i] = incl - v;
    if (tid == 255) g_bsum[blockIdx.x] = incl;
}
__global__ void scan2_kernel() {
    __shared__ int sh[2][256];
    int tid = threadIdx.x;
    int v = (tid < SCAN_BLOCKS) ? g_bsum[tid] : 0;
    sh[0][tid] = v;
    __syncthreads();
    int cur = 0;
#pragma unroll
    for (int s = 1; s < 256; s <<= 1) {
        int nxt = cur ^ 1;
        int t = sh[cur][tid];
        if (tid >= s) t += sh[cur][tid - s];
        sh[nxt][tid] = t;
        cur = nxt;
        __syncthreads();
    }
    if (tid < SCAN_BLOCKS) g_boff[tid] = sh[cur][tid] - v;
}
__global__ void scan3_kernel() {
    int i = blockIdx.x * 256 + threadIdx.x;
    if (i < N_NODES) {
        int st = g_start[i] + g_boff[blockIdx.x];
        g_start[i]  = st;
        g_cursor[i] = st;
    }
}

__global__ void scatter_kernel(const void* __restrict__ eiv) {
    int e0 = (blockIdx.x * 256 + threadIdx.x) * 4;
    if (e0 >= N_EDGES) return;
    int s0, s1, s2, s3, d0, d1, d2, d3;
    if (g_idx_is64) {
        const longlong2* ps = (const longlong2*)((const long long*)eiv + e0);
        const longlong2* pd = (const longlong2*)((const long long*)eiv + N_EDGES + e0);
        longlong2 a = __ldg(ps), c = __ldg(ps + 1);
        longlong2 e = __ldg(pd), f = __ldg(pd + 1);
        s0 = (int)a.x; s1 = (int)a.y; s2 = (int)c.x; s3 = (int)c.y;
        d0 = (int)e.x; d1 = (int)e.y; d2 = (int)f.x; d3 = (int)f.y;
    } else {
        int4 a = __ldg((const int4*)((const int*)eiv + e0));
        int4 e = __ldg((const int4*)((const int*)eiv + N_EDGES + e0));
        s0 = a.x; s1 = a.y; s2 = a.z; s3 = a.w;
        d0 = e.x; d1 = e.y; d2 = e.z; d3 = e.w;
    }
    g_ssrc[atomicAdd(&g_cursor[d0], 1)] = s0;
    g_ssrc[atomicAdd(&g_cursor[d1], 1)] = s1;
    g_ssrc[atomicAdd(&g_cursor[d2], 1)] = s2;
    g_ssrc[atomicAdd(&g_cursor[d3], 1)] = s3;
}

// ---------------- layer-1 aggregation: smem-staged chunks --------------------
__global__ __launch_bounds__(256) void agg1_kernel(const float* __restrict__ b1) {
    __shared__ float sx[8][4][32];
    __shared__ int   ss[8][32];
    int wid = threadIdx.x >> 5;
    int n = (blockIdx.x * blockDim.x + threadIdx.x) >> 5;
    if (n >= N_NODES) return;
    int lane = threadIdx.x & 31;
    int head = lane >> 3;
    int s0 = g_start[n];
    int c  = g_cnt[n];
    float4 adv = *(const float4*)(g_ad1 + n * 4);

    float a0=0,a1=0,a2=0,a3=0,a4=0,a5=0,a6=0,a7=0, denom=0.f;

    for (int base = 0; base < c; base += 32) {
        int m = min(32, c - base);
        if (lane < m) {
            int s = __ldg(g_ssrc + s0 + base + lane);
            float4 av = __ldg((const float4*)(g_as1 + s * 4));
            ss[wid][lane]    = s;
            sx[wid][0][lane] = __expf(lrelu(av.x + adv.x));
            sx[wid][1][lane] = __expf(lrelu(av.y + adv.y));
            sx[wid][2][lane] = __expf(lrelu(av.z + adv.z));
            sx[wid][3][lane] = __expf(lrelu(av.w + adv.w));
        }
        __syncwarp();
#pragma unroll 2
        for (int j = 0; j < m; j++) {
            int   s  = ss[wid][j];
            float xh = sx[wid][head][j];
            const float4* hp = (const float4*)(g_h1 + (size_t)s * L1_OUT + (lane << 3));
            float4 v0 = __ldg(hp), v1 = __ldg(hp + 1);
            denom += xh;
            a0 = fmaf(xh, v0.x, a0); a1 = fmaf(xh, v0.y, a1);
            a2 = fmaf(xh, v0.z, a2); a3 = fmaf(xh, v0.w, a3);
            a4 = fmaf(xh, v1.x, a4); a5 = fmaf(xh, v1.y, a5);
            a6 = fmaf(xh, v1.z, a6); a7 = fmaf(xh, v1.w, a7);
        }
        __syncwarp();
    }

    float inv = 1.0f / (denom + EPS);
    int col = lane * 8;
    float4 bA = *(const float4*)(b1 + col);
    float4 bB = *(const float4*)(b1 + col + 4);
    float4 oA, oB;
    oA.x = fmaxf(0.f, fmaf(a0, inv, bA.x));
    oA.y = fmaxf(0.f, fmaf(a1, inv, bA.y));
    oA.z = fmaxf(0.f, fmaf(a2, inv, bA.z));
    oA.w = fmaxf(0.f, fmaf(a3, inv, bA.w));
    oB.x = fmaxf(0.f, fmaf(a4, inv, bB.x));
    oB.y = fmaxf(0.f, fmaf(a5, inv, bB.y));
    oB.z = fmaxf(0.f, fmaf(a6, inv, bB.z));
    oB.w = fmaxf(0.f, fmaf(a7, inv, bB.w));
    *(float4*)(g_out1 + (size_t)n * L1_OUT + col)     = oA;
    *(float4*)(g_out1 + (size_t)n * L1_OUT + col + 4) = oB;
}

// ---------------- GEMM2 fused with alpha2 ------------------------------------
__global__ __launch_bounds__(256) void gemm2_kernel(
    const float* __restrict__ W2,
    const float* __restrict__ a_src, const float* __restrict__ a_dst)
{
    __shared__ float As[32][128];
    __shared__ float Bs[32][40];
    int tid = threadIdx.x;
    int tr = tid >> 3, tc = tid & 7;
    int bm = blockIdx.x * 128;

    int arow = tid >> 1;
    int acol = (tid & 1) * 16;
    const float* Aptr = g_out1 + (size_t)(bm + arow) * L1_OUT + acol;
    bool aval = (bm + arow) < N_NODES;
    int bidx = tid * 5;

    float4 sa[4];
    float  sb[5];
    float4 z = make_float4(0.f, 0.f, 0.f, 0.f);
#pragma unroll
    for (int q = 0; q < 4; q++)
        sa[q] = aval ? __ldg((const float4*)(Aptr + q * 4)) : z;
#pragma unroll
    for (int j = 0; j < 5; j++) sb[j] = __ldg(W2 + bidx + j);

    float acc[4][5] = {};

    for (int kk = 0; kk < L1_OUT / 32; kk++) {
        __syncthreads();
#pragma unroll
        for (int q = 0; q < 4; q++) {
            As[acol + q * 4 + 0][arow] = sa[q].x;
            As[acol + q * 4 + 1][arow] = sa[q].y;
            As[acol + q * 4 + 2][arow] = sa[q].z;
            As[acol + q * 4 + 3][arow] = sa[q].w;
        }
#pragma unroll
        for (int j = 0; j < 5; j++) ((float*)Bs)[bidx + j] = sb[j];
        __syncthreads();
        if (kk < L1_OUT / 32 - 1) {
            int k0 = (kk + 1) * 32;
#pragma unroll
            for (int q = 0; q < 4; q++)
                sa[q] = aval ? __ldg((const float4*)(Aptr + k0 + q * 4)) : z;
#pragma unroll
            for (int j = 0; j < 5; j++) sb[j] = __ldg(W2 + k0 * CLASSES + bidx + j);
        }
#pragma unroll
        for (int k = 0; k < 32; k++) {
            float4 av = *(const float4*)&As[k][tr * 4];
            float a[4] = {av.x, av.y, av.z, av.w};
            float b[5];
#pragma unroll
            for (int j = 0; j < 5; j++) b[j] = Bs[k][tc * 5 + j];
#pragma unroll
            for (int x = 0; x < 4; x++)
#pragma unroll
                for (int y = 0; y < 5; y++)
                    acc[x][y] = fmaf(a[x], b[y], acc[x][y]);
        }
    }

    float asv[5], adv[5];
#pragma unroll
    for (int y = 0; y < 5; y++) {
        asv[y] = __ldg(a_src + tc * 5 + y);
        adv[y] = __ldg(a_dst + tc * 5 + y);
    }
    float ps[4], pd[4];
#pragma unroll
    for (int x = 0; x < 4; x++) {
        float s = 0.f, d = 0.f;
#pragma unroll
        for (int y = 0; y < 5; y++) {
            s = fmaf(acc[x][y], asv[y], s);
            d = fmaf(acc[x][y], adv[y], d);
        }
        ps[x] = s; pd[x] = d;
    }
#pragma unroll
    for (int s = 1; s < 8; s <<= 1) {
#pragma unroll
        for (int x = 0; x < 4; x++) {
            ps[x] += __shfl_xor_sync(0xffffffffu, ps[x], s);
            pd[x] += __shfl_xor_sync(0xffffffffu, pd[x], s);
        }
    }
#pragma unroll
    for (int x = 0; x < 4; x++) {
        int r = bm + tr * 4 + x;
        if (r < N_NODES) {
            float* cp = g_h2 + (size_t)r * CLASSES + tc * 5;
#pragma unroll
            for (int y = 0; y < 5; y++) cp[y] = acc[x][y];
            if (tc == 0) {
                g_as2[r] = ps[x];
                g_ad2[r] = pd[x];
            }
        }
    }
}

// ---------------- layer-2 aggregation + fused log_softmax -------------------
__global__ __launch_bounds__(256) void agg2_kernel(const float* __restrict__ b2,
                                                   float* __restrict__ out) {
    __shared__ float sx[8][32];
    __shared__ int   ss[8][32];
    int wid = threadIdx.x >> 5;
    int n = (blockIdx.x * blockDim.x + threadIdx.x) >> 5;
    if (n >= N_NODES) return;
    int lane = threadIdx.x & 31;
    bool hi = lane < 8;
    int s0 = g_start[n];
    int c  = g_cnt[n];
    float adn = __ldg(g_ad2 + n);

    float acc0 = 0.f, acc1 = 0.f, denom = 0.f;
    for (int base = 0; base < c; base += 32) {
        int m = min(32, c - base);
        if (lane < m) {
            int s = __ldg(g_ssrc + s0 + base + lane);
            float e = __ldg(g_as2 + s);
            ss[wid][lane] = s;
            sx[wid][lane] = __expf(lrelu(e + adn));
        }
        __syncwarp();
#pragma unroll 2
        for (int j = 0; j < m; j++) {
            int   s = ss[wid][j];
            float x = sx[wid][j];
            const float* hp = g_h2 + (size_t)s * CLASSES;
            float h0 = __ldg(hp + lane);
            float h1 = hi ? __ldg(hp + 32 + lane) : 0.f;
            denom += x;
            acc0 = fmaf(x, h0, acc0);
            acc1 = fmaf(x, h1, acc1);
        }
        __syncwarp();
    }
    float inv = 1.0f / (denom + EPS);
    float o0 = fmaf(acc0, inv, __ldg(b2 + lane));
    float o1 = hi ? fmaf(acc1, inv, __ldg(b2 + 32 + lane)) : -1e30f;

    float mx = warpMax(fmaxf(o0, o1));
    float se = __expf(o0 - mx) + (hi ? __expf(o1 - mx) : 0.f);
    se = warpSum(se);
    float ls = __logf(se);
    out[(size_t)n * CLASSES + lane] = o0 - mx - ls;
    if (hi) out[(size_t)n * CLASSES + 32 + lane] = o1 - mx - ls;
}

// ---------------- launch -----------------------------------------------------
extern "C" void kernel_launch(void* const* d_in, const int* in_sizes, int n_in,
                              void* d_out, int out_size) {
    const float* x    = (const float*)d_in[0];
    const void*  ei   = d_in[1];
    const float* W1   = (const float*)d_in[2];
    const float* asr1 = (const float*)d_in[3];
    const float* adt1 = (const float*)d_in[4];
    const float* b1   = (const float*)d_in[5];
    const float* W2   = (const float*)d_in[6];
    const float* asr2 = (const float*)d_in[7];
    const float* adt2 = (const float*)d_in[8];
    const float* b2   = (const float*)d_in[9];
    float* out = (float*)d_out;

    zero_init_kernel<<<(N_NODES + 255) / 256, 256>>>();
    detect_kernel<<<(N_EDGES + 255) / 256, 256>>>((const long long*)ei);

    // GEMM1 (all tiles) + hist fused in one grid
    kMain<<<GEMM1_UNITS + EDGE_BLOCKS, 256>>>(x, W1, asr1, adt1, ei);

    scan1_kernel<<<SCAN_BLOCKS, 256>>>();
    scan2_kernel<<<1, 256>>>();
    scan3_kernel<<<SCAN_BLOCKS, 256>>>();
    scatter_kernel<<<EDGE_BLOCKS, 256>>>(ei);

    agg1_kernel<<<(N_NODES + 7) / 8, 256>>>(b1);
    gemm2_kernel<<<(N_NODES + 127) / 128, 256>>>(W2, asr2, adt2);
    agg2_kernel<<<(N_NODES + 7) / 8, 256>>>(b2, out);
}

// round 5
// speedup vs baseline: 1.2743x; 1.1591x over previous
#include <cuda_runtime.h>
#include <cuda_fp16.h>
#include <cstdint>

#define N_NODES 50000
#define N_EDGES 800000
#define F_IN    128
#define HID     64
#define HEADS   4
#define L1_OUT  (HEADS*HID)   // 256
#define CLASSES 40
#define NEG_SLOPE 0.2f
#define EPS 1e-16f

#define GEMM1_UNITS 782            // 391 row tiles * 2 col tiles
#define EDGE_BLOCKS 782            // ceil(800000 / (256*4))
#define SCAN_BLOCKS 196            // ceil(50000/256)

// ---------------- scratch --------------------------------------------------
__device__ __align__(16) __half g_h1h[(size_t)N_NODES * L1_OUT];   // fp16 messages
__device__ __align__(16) float g_out1[(size_t)N_NODES * L1_OUT];
__device__ __align__(16) float g_h2  [(size_t)N_NODES * CLASSES];
__device__ __align__(16) float g_as1[N_NODES * HEADS];
__device__ __align__(16) float g_ad1[N_NODES * HEADS];
__device__ float g_as2[N_NODES];
__device__ float g_ad2[N_NODES];
__device__ int   g_cnt[N_NODES];
__device__ int   g_start[N_NODES];
__device__ int   g_cursor[N_NODES];
__device__ int   g_ssrc[N_EDGES];
__device__ int   g_idx_bad;        // 0 invariant between launches; reset by agg1
__device__ int   g_bsum[SCAN_BLOCKS];
__device__ int   g_boff[SCAN_BLOCKS];

// ---------------- helpers ---------------------------------------------------
__device__ __forceinline__ float warpMax(float v) {
#pragma unroll
    for (int s = 16; s > 0; s >>= 1)
        v = fmaxf(v, __shfl_xor_sync(0xffffffffu, v, s));
    return v;
}
__device__ __forceinline__ float warpSum(float v) {
#pragma unroll
    for (int s = 16; s > 0; s >>= 1)
        v += __shfl_xor_sync(0xffffffffu, v, s);
    return v;
}
__device__ __forceinline__ float lrelu(float x) {
    return (x > 0.f) ? x : NEG_SLOPE * x;
}

// ---------------- prep: zero hist + int64/int32 detection (one kernel) -------
__global__ void prep_kernel(const long long* __restrict__ ei) {
    int i = blockIdx.x * blockDim.x + threadIdx.x;
    if (i < N_NODES) g_cnt[i] = 0;
    if (i < N_EDGES) {
        long long v = ei[i];
        if (v < 0 || v >= N_NODES) g_idx_bad = 1;   // only ever set; reset later
    }
}

// ---------------- GEMM1 tile (128x128, BK=16, TM=TN=8) + fused alpha1 --------
__device__ __forceinline__ void gemm1_tile(
    int unit, float* sm,
    const float* __restrict__ A, const float* __restrict__ B,
    const float* __restrict__ a_src, const float* __restrict__ a_dst)
{
    float* As = sm;            // [16][128]
    float* Bs = sm + 2048;     // [16][128]
    int tid = threadIdx.x;
    int tr = tid >> 4, tc = tid & 15;
    int bn = (unit & 1) * 128;
    int bm = (unit >> 1) * 128;

    int arow = tid >> 1;
    int acol = (tid & 1) * 8;
    int brow = tid >> 4;
    int bcol = (tid & 15) * 8;

    const float* Aptr = A + (size_t)(bm + arow) * F_IN + acol;
    bool aval = (bm + arow) < N_NODES;
    const float* Bptr = B + (size_t)brow * L1_OUT + bn + bcol;

    float4 z = make_float4(0.f, 0.f, 0.f, 0.f);
    float4 ra0 = aval ? __ldg((const float4*)Aptr)       : z;
    float4 ra1 = aval ? __ldg((const float4*)(Aptr + 4)) : z;
    float4 rb0 = __ldg((const float4*)Bptr);
    float4 rb1 = __ldg((const float4*)(Bptr + 4));

    float acc[8][8] = {};

    for (int kk = 0; kk < F_IN / 16; kk++) {
        __syncthreads();
        As[(acol + 0) * 128 + arow] = ra0.x; As[(acol + 1) * 128 + arow] = ra0.y;
        As[(acol + 2) * 128 + arow] = ra0.z; As[(acol + 3) * 128 + arow] = ra0.w;
        As[(acol + 4) * 128 + arow] = ra1.x; As[(acol + 5) * 128 + arow] = ra1.y;
        As[(acol + 6) * 128 + arow] = ra1.z; As[(acol + 7) * 128 + arow] = ra1.w;
        *(float4*)&Bs[brow * 128 + bcol]     = rb0;
        *(float4*)&Bs[brow * 128 + bcol + 4] = rb1;
        __syncthreads();
        if (kk < F_IN / 16 - 1) {
            int k0 = (kk + 1) * 16;
            ra0 = aval ? __ldg((const float4*)(Aptr + k0))     : z;
            ra1 = aval ? __ldg((const float4*)(Aptr + k0 + 4)) : z;
            rb0 = __ldg((const float4*)(Bptr + (size_t)k0 * L1_OUT));
            rb1 = __ldg((const float4*)(Bptr + (size_t)k0 * L1_OUT + 4));
        }
#pragma unroll
        for (int k = 0; k < 16; k++) {
            float4 av0 = *(const float4*)&As[k * 128 + tr * 8];
            float4 av1 = *(const float4*)&As[k * 128 + tr * 8 + 4];
            float4 bv0 = *(const float4*)&Bs[k * 128 + tc * 8];
            float4 bv1 = *(const float4*)&Bs[k * 128 + tc * 8 + 4];
            float a[8] = {av0.x, av0.y, av0.z, av0.w, av1.x, av1.y, av1.z, av1.w};
            float b[8] = {bv0.x, bv0.y, bv0.z, bv0.w, bv1.x, bv1.y, bv1.z, bv1.w};
#pragma unroll
            for (int x = 0; x < 8; x++)
#pragma unroll
                for (int y = 0; y < 8; y++)
                    acc[x][y] = fmaf(a[x], b[y], acc[x][y]);
        }
    }

    int head = (bn >> 6) + (tc >> 3);
    int chbase = (tc & 7) * 8;
    float asv[8], adv[8];
#pragma unroll
    for (int y = 0; y < 8; y++) {
        asv[y] = __ldg(a_src + head * HID + chbase + y);
        adv[y] = __ldg(a_dst + head * HID + chbase + y);
    }
    float ps[8], pd[8];
#pragma unroll
    for (int x = 0; x < 8; x++) {
        float s = 0.f, d = 0.f;
#pragma unroll
        for (int y = 0; y < 8; y++) {
            s = fmaf(acc[x][y], asv[y], s);
            d = fmaf(acc[x][y], adv[y], d);
        }
        ps[x] = s; pd[x] = d;
    }
#pragma unroll
    for (int s = 1; s < 8; s <<= 1) {
#pragma unroll
        for (int x = 0; x < 8; x++) {
            ps[x] += __shfl_xor_sync(0xffffffffu, ps[x], s);
            pd[x] += __shfl_xor_sync(0xffffffffu, pd[x], s);
        }
    }
#pragma unroll
    for (int x = 0; x < 8; x++) {
        int r = bm + tr * 8 + x;
        if (r < N_NODES) {
            // store h1 as fp16 (half2 x4 = 16B)
            __half2 hp[4];
            hp[0] = __floats2half2_rn(acc[x][0], acc[x][1]);
            hp[1] = __floats2half2_rn(acc[x][2], acc[x][3]);
            hp[2] = __floats2half2_rn(acc[x][4], acc[x][5]);
            hp[3] = __floats2half2_rn(acc[x][6], acc[x][7]);
            *(uint4*)(g_h1h + (size_t)r * L1_OUT + bn + tc * 8) = *(uint4*)hp;
            if ((tc & 7) == 0) {
                g_as1[r * 4 + head] = ps[x];
                g_ad1[r * 4 + head] = pd[x];
            }
        }
    }
}

__device__ __forceinline__ void hist_block(int b, const void* __restrict__ eiv) {
    int e0 = (b * 256 + threadIdx.x) * 4;
    if (e0 >= N_EDGES) return;
    int d0, d1, d2, d3;
    if (!g_idx_bad) {
        const longlong2* p = (const longlong2*)((const long long*)eiv + N_EDGES + e0);
        longlong2 a = __ldg(p), c = __ldg(p + 1);
        d0 = (int)a.x; d1 = (int)a.y; d2 = (int)c.x; d3 = (int)c.y;
    } else {
        int4 a = __ldg((const int4*)((const int*)eiv + N_EDGES + e0));
        d0 = a.x; d1 = a.y; d2 = a.z; d3 = a.w;
    }
    atomicAdd(&g_cnt[d0], 1);
    atomicAdd(&g_cnt[d1], 1);
    atomicAdd(&g_cnt[d2], 1);
    atomicAdd(&g_cnt[d3], 1);
}

// GEMM1 (all 782 tiles) + hist (independent) in ONE grid
__global__ __launch_bounds__(256) void kMain(
    const float* __restrict__ x, const float* __restrict__ W1,
    const float* __restrict__ as, const float* __restrict__ ad,
    const void* __restrict__ ei)
{
    __shared__ float sm[4096];
    if (blockIdx.x < GEMM1_UNITS) gemm1_tile(blockIdx.x, sm, x, W1, as, ad);
    else                          hist_block(blockIdx.x - GEMM1_UNITS, ei);
}

// ---------------- two-level scan ---------------------------------------------
__global__ void scan1_kernel() {
    __shared__ int sh[2][256];
    int tid = threadIdx.x;
    int i = blockIdx.x * 256 + tid;
    int v = (i < N_NODES) ? g_cnt[i] : 0;
    sh[0][tid] = v;
    __syncthreads();
    int cur = 0;
#pragma unroll
    for (int s = 1; s < 256; s <<= 1) {
        int nxt = cur ^ 1;
        int t = sh[cur][tid];
        if (tid >= s) t += sh[cur][tid - s];
        sh[nxt][tid] = t;
        cur = nxt;
        __syncthreads();
    }
    int incl = sh[cur][tid];
    if (i < N_NODES) g_start[i] = incl - v;
    if (tid == 255) g_bsum[blockIdx.x] = incl;
}
__global__ void scan2_kernel() {
    __shared__ int sh[2][256];
    int tid = threadIdx.x;
    int v = (tid < SCAN_BLOCKS) ? g_bsum[tid] : 0;
    sh[0][tid] = v;
    __syncthreads();
    int cur = 0;
#pragma unroll
    for (int s = 1; s < 256; s <<= 1) {
        int nxt = cur ^ 1;
        int t = sh[cur][tid];
        if (tid >= s) t += sh[cur][tid - s];
        sh[nxt][tid] = t;
        cur = nxt;
        __syncthreads();
    }
    if (tid < SCAN_BLOCKS) g_boff[tid] = sh[cur][tid] - v;
}
__global__ void scan3_kernel() {
    int i = blockIdx.x * 256 + threadIdx.x;
    if (i < N_NODES) {
        int st = g_start[i] + g_boff[blockIdx.x];
        g_start[i]  = st;
        g_cursor[i] = st;
    }
}

__global__ void scatter_kernel(const void* __restrict__ eiv) {
    int e0 = (blockIdx.x * 256 + threadIdx.x) * 4;
    if (e0 >= N_EDGES) return;
    int s0, s1, s2, s3, d0, d1, d2, d3;
    if (!g_idx_bad) {
        const longlong2* ps = (const longlong2*)((const long long*)eiv + e0);
        const longlong2* pd = (const longlong2*)((const long long*)eiv + N_EDGES + e0);
        longlong2 a = __ldg(ps), c = __ldg(ps + 1);
        longlong2 e = __ldg(pd), f = __ldg(pd + 1);
        s0 = (int)a.x; s1 = (int)a.y; s2 = (int)c.x; s3 = (int)c.y;
        d0 = (int)e.x; d1 = (int)e.y; d2 = (int)f.x; d3 = (int)f.y;
    } else {
        int4 a = __ldg((const int4*)((const int*)eiv + e0));
        int4 e = __ldg((const int4*)((const int*)eiv + N_EDGES + e0));
        s0 = a.x; s1 = a.y; s2 = a.z; s3 = a.w;
        d0 = e.x; d1 = e.y; d2 = e.z; d3 = e.w;
    }
    g_ssrc[atomicAdd(&g_cursor[d0], 1)] = s0;
    g_ssrc[atomicAdd(&g_cursor[d1], 1)] = s1;
    g_ssrc[atomicAdd(&g_cursor[d2], 1)] = s2;
    g_ssrc[atomicAdd(&g_cursor[d3], 1)] = s3;
}

// ---------------- layer-1 aggregation: fp16 rows, fp32 accumulate ------------
__global__ __launch_bounds__(256) void agg1_kernel(const float* __restrict__ b1) {
    __shared__ float sx[8][4][32];
    __shared__ int   ss[8][32];
    int wid = threadIdx.x >> 5;
    int gt = blockIdx.x * blockDim.x + threadIdx.x;
    if (gt == 0) g_idx_bad = 0;          // restore invariant (last reader was scatter)
    int n = gt >> 5;
    if (n >= N_NODES) return;
    int lane = threadIdx.x & 31;
    int head = lane >> 3;
    int s0 = g_start[n];
    int c  = g_cnt[n];
    float4 adv = *(const float4*)(g_ad1 + n * 4);

    float a0=0,a1=0,a2=0,a3=0,a4=0,a5=0,a6=0,a7=0, denom=0.f;

    for (int base = 0; base < c; base += 32) {
        int m = min(32, c - base);
        if (lane < m) {
            int s = __ldg(g_ssrc + s0 + base + lane);
            float4 av = __ldg((const float4*)(g_as1 + s * 4));
            ss[wid][lane]    = s;
            sx[wid][0][lane] = __expf(lrelu(av.x + adv.x));
            sx[wid][1][lane] = __expf(lrelu(av.y + adv.y));
            sx[wid][2][lane] = __expf(lrelu(av.z + adv.z));
            sx[wid][3][lane] = __expf(lrelu(av.w + adv.w));
        }
        __syncwarp();
#pragma unroll 2
        for (int j = 0; j < m; j++) {
            int   s  = ss[wid][j];
            float xh = sx[wid][head][j];
            uint4 u = __ldg((const uint4*)(g_h1h + (size_t)s * L1_OUT + (lane << 3)));
            float2 f0 = __half22float2(*(__half2*)&u.x);
            float2 f1 = __half22float2(*(((__half2*)&u.x) + 1));
            float2 f2 = __half22float2(*(__half2*)&u.z);
            float2 f3 = __half22float2(*(((__half2*)&u.z) + 1));
            denom += xh;
            a0 = fmaf(xh, f0.x, a0); a1 = fmaf(xh, f0.y, a1);
            a2 = fmaf(xh, f1.x, a2); a3 = fmaf(xh, f1.y, a3);
            a4 = fmaf(xh, f2.x, a4); a5 = fmaf(xh, f2.y, a5);
            a6 = fmaf(xh, f3.x, a6); a7 = fmaf(xh, f3.y, a7);
        }
        __syncwarp();
    }

    float inv = 1.0f / (denom + EPS);
    int col = lane * 8;
    float4 bA = *(const float4*)(b1 + col);
    float4 bB = *(const float4*)(b1 + col + 4);
    float4 oA, oB;
    oA.x = fmaxf(0.f, fmaf(a0, inv, bA.x));
    oA.y = fmaxf(0.f, fmaf(a1, inv, bA.y));
    oA.z = fmaxf(0.f, fmaf(a2, inv, bA.z));
    oA.w = fmaxf(0.f, fmaf(a3, inv, bA.w));
    oB.x = fmaxf(0.f, fmaf(a4, inv, bB.x));
    oB.y = fmaxf(0.f, fmaf(a5, inv, bB.y));
    oB.z = fmaxf(0.f, fmaf(a6, inv, bB.z));
    oB.w = fmaxf(0.f, fmaf(a7, inv, bB.w));
    *(float4*)(g_out1 + (size_t)n * L1_OUT + col)     = oA;
    *(float4*)(g_out1 + (size_t)n * L1_OUT + col + 4) = oB;
}

// ---------------- GEMM2 fused with alpha2 ------------------------------------
__global__ __launch_bounds__(256) void gemm2_kernel(
    const float* __restrict__ W2,
    const float* __restrict__ a_src, const float* __restrict__ a_dst)
{
    __shared__ float As[32][128];
    __shared__ float Bs[32][40];
    int tid = threadIdx.x;
    int tr = tid >> 3, tc = tid & 7;
    int bm = blockIdx.x * 128;

    int arow = tid >> 1;
    int acol = (tid & 1) * 16;
    const float* Aptr = g_out1 + (size_t)(bm + arow) * L1_OUT + acol;
    bool aval = (bm + arow) < N_NODES;
    int bidx = tid * 5;

    float4 sa[4];
    float  sb[5];
    float4 z = make_float4(0.f, 0.f, 0.f, 0.f);
#pragma unroll
    for (int q = 0; q < 4; q++)
        sa[q] = aval ? __ldg((const float4*)(Aptr + q * 4)) : z;
#pragma unroll
    for (int j = 0; j < 5; j++) sb[j] = __ldg(W2 + bidx + j);

    float acc[4][5] = {};

    for (int kk = 0; kk < L1_OUT / 32; kk++) {
        __syncthreads();
#pragma unroll
        for (int q = 0; q < 4; q++) {
            As[acol + q * 4 + 0][arow] = sa[q].x;
            As[acol + q * 4 + 1][arow] = sa[q].y;
            As[acol + q * 4 + 2][arow] = sa[q].z;
            As[acol + q * 4 + 3][arow] = sa[q].w;
        }
#pragma unroll
        for (int j = 0; j < 5; j++) ((float*)Bs)[bidx + j] = sb[j];
        __syncthreads();
        if (kk < L1_OUT / 32 - 1) {
            int k0 = (kk + 1) * 32;
#pragma unroll
            for (int q = 0; q < 4; q++)
                sa[q] = aval ? __ldg((const float4*)(Aptr + k0 + q * 4)) : z;
#pragma unroll
            for (int j = 0; j < 5; j++) sb[j] = __ldg(W2 + k0 * CLASSES + bidx + j);
        }
#pragma unroll
        for (int k = 0; k < 32; k++) {
            float4 av = *(const float4*)&As[k][tr * 4];
            float a[4] = {av.x, av.y, av.z, av.w};
            float b[5];
#pragma unroll
            for (int j = 0; j < 5; j++) b[j] = Bs[k][tc * 5 + j];
#pragma unroll
            for (int x = 0; x < 4; x++)
#pragma unroll
                for (int y = 0; y < 5; y++)
                    acc[x][y] = fmaf(a[x], b[y], acc[x][y]);
        }
    }

    float asv[5], adv[5];
#pragma unroll
    for (int y = 0; y < 5; y++) {
        asv[y] = __ldg(a_src + tc * 5 + y);
        adv[y] = __ldg(a_dst + tc * 5 + y);
    }
    float ps[4], pd[4];
#pragma unroll
    for (int x = 0; x < 4; x++) {
        float s = 0.f, d = 0.f;
#pragma unroll
        for (int y = 0; y < 5; y++) {
            s = fmaf(acc[x][y], asv[y], s);
            d = fmaf(acc[x][y], adv[y], d);
        }
        ps[x] = s; pd[x] = d;
    }
#pragma unroll
    for (int s = 1; s < 8; s <<= 1) {
#pragma unroll
        for (int x = 0; x < 4; x++) {
            ps[x] += __shfl_xor_sync(0xffffffffu, ps[x], s);
            pd[x] += __shfl_xor_sync(0xffffffffu, pd[x], s);
        }
    }
#pragma unroll
    for (int x = 0; x < 4; x++) {
        int r = bm + tr * 4 + x;
        if (r < N_NODES) {
            float* cp = g_h2 + (size_t)r * CLASSES + tc * 5;
#pragma unroll
            for (int y = 0; y < 5; y++) cp[y] = acc[x][y];
            if (tc == 0) {
                g_as2[r] = ps[x];
                g_ad2[r] = pd[x];
            }
        }
    }
}

// ---------------- layer-2 aggregation + fused log_softmax -------------------
__global__ __launch_bounds__(256) void agg2_kernel(const float* __restrict__ b2,
                                                   float* __restrict__ out) {
    __shared__ float sx[8][32];
    __shared__ int   ss[8][32];
    int wid = threadIdx.x >> 5;
    int n = (blockIdx.x * blockDim.x + threadIdx.x) >> 5;
    if (n >= N_NODES) return;
    int lane = threadIdx.x & 31;
    bool hi = lane < 8;
    int s0 = g_start[n];
    int c  = g_cnt[n];
    float adn = __ldg(g_ad2 + n);

    float acc0 = 0.f, acc1 = 0.f, denom = 0.f;
    for (int base = 0; base < c; base += 32) {
        int m = min(32, c - base);
        if (lane < m) {
            int s = __ldg(g_ssrc + s0 + base + lane);
            float e = __ldg(g_as2 + s);
            ss[wid][lane] = s;
            sx[wid][lane] = __expf(lrelu(e + adn));
        }
        __syncwarp();
#pragma unroll 2
        for (int j = 0; j < m; j++) {
            int   s = ss[wid][j];
            float x = sx[wid][j];
            const float* hp = g_h2 + (size_t)s * CLASSES;
            float h0 = __ldg(hp + lane);
            float h1 = hi ? __ldg(hp + 32 + lane) : 0.f;
            denom += x;
            acc0 = fmaf(x, h0, acc0);
            acc1 = fmaf(x, h1, acc1);
        }
        __syncwarp();
    }
    float inv = 1.0f / (denom + EPS);
    float o0 = fmaf(acc0, inv, __ldg(b2 + lane));
    float o1 = hi ? fmaf(acc1, inv, __ldg(b2 + 32 + lane)) : -1e30f;

    float mx = warpMax(fmaxf(o0, o1));
    float se = __expf(o0 - mx) + (hi ? __expf(o1 - mx) : 0.f);
    se = warpSum(se);
    float ls = __logf(se);
    out[(size_t)n * CLASSES + lane] = o0 - mx - ls;
    if (hi) out[(size_t)n * CLASSES + 32 + lane] = o1 - mx - ls;
}

// ---------------- launch -----------------------------------------------------
extern "C" void kernel_launch(void* const* d_in, const int* in_sizes, int n_in,
                              void* d_out, int out_size) {
    const float* x    = (const float*)d_in[0];
    const void*  ei   = d_in[1];
    const float* W1   = (const float*)d_in[2];
    const float* asr1 = (const float*)d_in[3];
    const float* adt1 = (const float*)d_in[4];
    const float* b1   = (const float*)d_in[5];
    const float* W2   = (const float*)d_in[6];
    const float* asr2 = (const float*)d_in[7];
    const float* adt2 = (const float*)d_in[8];
    const float* b2   = (const float*)d_in[9];
    float* out = (float*)d_out;

    prep_kernel<<<(N_EDGES + 255) / 256, 256>>>((const long long*)ei);

    // GEMM1 (all tiles) + hist fused in one grid
    kMain<<<GEMM1_UNITS + EDGE_BLOCKS, 256>>>(x, W1, asr1, adt1, ei);

    scan1_kernel<<<SCAN_BLOCKS, 256>>>();
    scan2_kernel<<<1, 256>>>();
    scan3_kernel<<<SCAN_BLOCKS, 256>>>();
    scatter_kernel<<<EDGE_BLOCKS, 256>>>(ei);

    agg1_kernel<<<(N_NODES + 7) / 8, 256>>>(b1);
    gemm2_kernel<<<(N_NODES + 127) / 128, 256>>>(W2, asr2, adt2);
    agg2_kernel<<<(N_NODES + 7) / 8, 256>>>(b2, out);
}

// round 6
// speedup vs baseline: 1.6690x; 1.3097x over previous
#include <cuda_runtime.h>
#include <cuda_fp16.h>
#include <cstdint>

#define N_NODES 50000
#define N_EDGES 800000
#define F_IN    128
#define HID     64
#define HEADS   4
#define L1_OUT  (HEADS*HID)   // 256
#define CLASSES 40
#define NEG_SLOPE 0.2f
#define EPS 1e-16f

#define GEMM1_TILES 391            // ceil(50000/128), 256-wide
#define EDGE_BLOCKS 782            // ceil(800000 / (256*4))
#define SCAN_BLOCKS 196            // ceil(50000/256)

// ---------------- scratch --------------------------------------------------
__device__ __align__(16) __half g_h1h [(size_t)N_NODES * L1_OUT];   // fp16 layer-1 features
__device__ __align__(16) __half g_out1h[(size_t)N_NODES * L1_OUT];  // fp16 relu(layer1)
__device__ __align__(16) __half g_h2h [(size_t)N_NODES * CLASSES];  // fp16 layer-2 features
__device__ __align__(16) float g_as1[N_NODES * HEADS];
__device__ __align__(16) float g_ad1[N_NODES * HEADS];
__device__ float g_as2[N_NODES];
__device__ float g_ad2[N_NODES];
__device__ int   g_cnt[N_NODES];
__device__ int   g_start[N_NODES];
__device__ int   g_cursor[N_NODES];
__device__ int   g_ssrc[N_EDGES];
__device__ int   g_idx_bad;        // 0 between launches; set by prep, reset by agg1
__device__ int   g_total;          // scan offset accumulator

// ---------------- helpers ---------------------------------------------------
__device__ __forceinline__ float warpMax(float v) {
#pragma unroll
    for (int s = 16; s > 0; s >>= 1)
        v = fmaxf(v, __shfl_xor_sync(0xffffffffu, v, s));
    return v;
}
__device__ __forceinline__ float warpSum(float v) {
#pragma unroll
    for (int s = 16; s > 0; s >>= 1)
        v += __shfl_xor_sync(0xffffffffu, v, s);
    return v;
}
__device__ __forceinline__ float lrelu(float x) {
    return (x > 0.f) ? x : NEG_SLOPE * x;
}
__device__ __forceinline__ uint32_t smem_u32(const void* p) {
    return (uint32_t)__cvta_generic_to_shared(p);
}
__device__ __forceinline__ void ldmatrix_x4(uint32_t* r, uint32_t addr) {
    asm volatile("ldmatrix.sync.aligned.m8n8.x4.shared.b16 {%0,%1,%2,%3}, [%4];"
                 : "=r"(r[0]), "=r"(r[1]), "=r"(r[2]), "=r"(r[3]) : "r"(addr));
}
__device__ __forceinline__ void ldmatrix_x4_trans(uint32_t* r, uint32_t addr) {
    asm volatile("ldmatrix.sync.aligned.m8n8.x4.trans.shared.b16 {%0,%1,%2,%3}, [%4];"
                 : "=r"(r[0]), "=r"(r[1]), "=r"(r[2]), "=r"(r[3]) : "r"(addr));
}
__device__ __forceinline__ void mma16816(float* c, const uint32_t* a, const uint32_t* b) {
    asm volatile(
        "mma.sync.aligned.m16n8k16.row.col.f32.f16.f16.f32 "
        "{%0,%1,%2,%3}, {%4,%5,%6,%7}, {%8,%9}, {%0,%1,%2,%3};"
        : "+f"(c[0]), "+f"(c[1]), "+f"(c[2]), "+f"(c[3])
        : "r"(a[0]), "r"(a[1]), "r"(a[2]), "r"(a[3]), "r"(b[0]), "r"(b[1]));
}

// ---------------- prep: zero hist + dtype detection + total reset ------------
__global__ void prep_kernel(const long long* __restrict__ ei) {
    int i = blockIdx.x * blockDim.x + threadIdx.x;
    if (i == 0) g_total = 0;
    if (i < N_NODES) g_cnt[i] = 0;
    if (i < N_EDGES) {
        long long v = ei[i];
        if (v < 0 || v >= N_NODES) g_idx_bad = 1;
    }
}

// ---------------- GEMM1 via HMMA: 128x256 tile, fp16 in/fp32 acc -------------
// Warp w: rows (w>>2)*64..+64, cols (w&3)*64..+64 (= head w&3).
// smem: As [128][40] halves, Bs [32][264] halves (padded, ldmatrix-conflict-free)
#define APAD 40
#define BPAD 264
__device__ __forceinline__ void gemm1_tc(
    int unit, __half* smem,
    const float* __restrict__ A, const float* __restrict__ B,
    const float* __restrict__ a_src, const float* __restrict__ a_dst)
{
    __half* As = smem;                 // [128][APAD]
    __half* Bs = smem + 128 * APAD;    // [32][BPAD]
    const int tid = threadIdx.x;
    const int wid = tid >> 5, lane = tid & 31;
    const int bm = unit * 128;
    const int wm = (wid >> 2) * 64;
    const int wn = (wid & 3) * 64;
    const int head = wid & 3;

    const int ar = tid >> 1;            // 0..127
    const int ac = (tid & 1) * 16;      // 0/16
    const int br = tid >> 3;            // 0..31
    const int bc = (tid & 7) * 32;      // 0..224

    const float* Ap = A + (size_t)(bm + ar) * F_IN + ac;
    const bool aval = (bm + ar) < N_NODES;
    const float* Bp = B + (size_t)br * L1_OUT + bc;
    const float4 z = make_float4(0.f, 0.f, 0.f, 0.f);

    float acc[4][8][4];
#pragma unroll
    for (int i = 0; i < 4; i++)
#pragma unroll
        for (int j = 0; j < 8; j++)
#pragma unroll
            for (int q = 0; q < 4; q++) acc[i][j][q] = 0.f;

    float4 ra[4], rb[8];
#pragma unroll
    for (int q = 0; q < 4; q++) ra[q] = aval ? __ldg((const float4*)(Ap + q * 4)) : z;
#pragma unroll
    for (int q = 0; q < 8; q++) rb[q] = __ldg((const float4*)(Bp + q * 4));

    // precompute ldmatrix base addresses (per-lane)
    uint32_t a_addr[4], b_addr[4];
#pragma unroll
    for (int mi = 0; mi < 4; mi++)
        a_addr[mi] = smem_u32(As + (wm + mi * 16 + (lane & 15)) * APAD + (lane >> 4) * 8);
#pragma unroll
    for (int nj = 0; nj < 4; nj++)
        b_addr[nj] = smem_u32(Bs + (lane & 15) * BPAD + wn + nj * 16 + (lane >> 4) * 8);

    for (int kk = 0; kk < F_IN / 32; kk++) {
        if (kk > 0) __syncthreads();
        {
            __half2* Arow = (__half2*)(As + ar * APAD + ac);
#pragma unroll
            for (int q = 0; q < 4; q++) {
                Arow[q * 2]     = __floats2half2_rn(ra[q].x, ra[q].y);
                Arow[q * 2 + 1] = __floats2half2_rn(ra[q].z, ra[q].w);
            }
            __half2* Brow = (__half2*)(Bs + br * BPAD + bc);
#pragma unroll
            for (int q = 0; q < 8; q++) {
                Brow[q * 2]     = __floats2half2_rn(rb[q].x, rb[q].y);
                Brow[q * 2 + 1] = __floats2half2_rn(rb[q].z, rb[q].w);
            }
        }
        __syncthreads();
        if (kk < F_IN / 32 - 1) {
            int k0 = (kk + 1) * 32;
#pragma unroll
            for (int q = 0; q < 4; q++)
                ra[q] = aval ? __ldg((const float4*)(Ap + k0 + q * 4)) : z;
#pragma unroll
            for (int q = 0; q < 8; q++)
                rb[q] = __ldg((const float4*)(Bp + (size_t)k0 * L1_OUT + q * 4));
        }
#pragma unroll
        for (int k16 = 0; k16 < 2; k16++) {
            uint32_t af[4][4], bf[8][2];
#pragma unroll
            for (int mi = 0; mi < 4; mi++)
                ldmatrix_x4(af[mi], a_addr[mi] + k16 * 32);           // +16 halves
#pragma unroll
            for (int nj = 0; nj < 4; nj++) {
                uint32_t t[4];
                ldmatrix_x4_trans(t, b_addr[nj] + k16 * 16 * BPAD * 2);
                bf[nj * 2][0] = t[0]; bf[nj * 2][1] = t[1];
                bf[nj * 2 + 1][0] = t[2]; bf[nj * 2 + 1][1] = t[3];
            }
#pragma unroll
            for (int mi = 0; mi < 4; mi++)
#pragma unroll
                for (int ni = 0; ni < 8; ni++)
                    mma16816(acc[mi][ni], af[mi], bf[ni]);
        }
    }

    // ---- epilogue: fused alpha dots + fp16 store ----
    float as0[8], as1[8], ad0[8], ad1[8];
    int cb = (lane & 3) * 2;
#pragma unroll
    for (int ni = 0; ni < 8; ni++) {
        int col = wn + ni * 8 + cb;
        as0[ni] = __ldg(a_src + col); as1[ni] = __ldg(a_src + col + 1);
        ad0[ni] = __ldg(a_dst + col); ad1[ni] = __ldg(a_dst + col + 1);
    }
#pragma unroll
    for (int mi = 0; mi < 4; mi++) {
        float sl = 0.f, sh = 0.f, dl = 0.f, dh = 0.f;
#pragma unroll
        for (int ni = 0; ni < 8; ni++) {
            sl = fmaf(acc[mi][ni][0], as0[ni], fmaf(acc[mi][ni][1], as1[ni], sl));
            sh = fmaf(acc[mi][ni][2], as0[ni], fmaf(acc[mi][ni][3], as1[ni], sh));
            dl = fmaf(acc[mi][ni][0], ad0[ni], fmaf(acc[mi][ni][1], ad1[ni], dl));
            dh = fmaf(acc[mi][ni][2], ad0[ni], fmaf(acc[mi][ni][3], ad1[ni], dh));
        }
        // reduce over the 4 lanes sharing a row
#pragma unroll
        for (int s = 1; s < 4; s <<= 1) {
            sl += __shfl_xor_sync(0xffffffffu, sl, s);
            sh += __shfl_xor_sync(0xffffffffu, sh, s);
            dl += __shfl_xor_sync(0xffffffffu, dl, s);
            dh += __shfl_xor_sync(0xffffffffu, dh, s);
        }
        int row_lo = bm + wm + mi * 16 + (lane >> 2);
        int row_hi = row_lo + 8;
        if ((lane & 3) == 0) {
            if (row_lo < N_NODES) { g_as1[row_lo * 4 + head] = sl; g_ad1[row_lo * 4 + head] = dl; }
            if (row_hi < N_NODES) { g_as1[row_hi * 4 + head] = sh; g_ad1[row_hi * 4 + head] = dh; }
        }
        if (row_lo < N_NODES) {
            __half* p = g_h1h + (size_t)row_lo * L1_OUT + wn + cb;
#pragma unroll
            for (int ni = 0; ni < 8; ni++)
                *(__half2*)(p + ni * 8) = __floats2half2_rn(acc[mi][ni][0], acc[mi][ni][1]);
        }
        if (row_hi < N_NODES) {
            __half* p = g_h1h + (size_t)row_hi * L1_OUT + wn + cb;
#pragma unroll
            for (int ni = 0; ni < 8; ni++)
                *(__half2*)(p + ni * 8) = __floats2half2_rn(acc[mi][ni][2], acc[mi][ni][3]);
        }
    }
}

__device__ __forceinline__ void hist_block(int b, const void* __restrict__ eiv) {
    int e0 = (b * 256 + threadIdx.x) * 4;
    if (e0 >= N_EDGES) return;
    int d0, d1, d2, d3;
    if (!g_idx_bad) {
        const longlong2* p = (const longlong2*)((const long long*)eiv + N_EDGES + e0);
        longlong2 a = __ldg(p), c = __ldg(p + 1);
        d0 = (int)a.x; d1 = (int)a.y; d2 = (int)c.x; d3 = (int)c.y;
    } else {
        int4 a = __ldg((const int4*)((const int*)eiv + N_EDGES + e0));
        d0 = a.x; d1 = a.y; d2 = a.z; d3 = a.w;
    }
    atomicAdd(&g_cnt[d0], 1);
    atomicAdd(&g_cnt[d1], 1);
    atomicAdd(&g_cnt[d2], 1);
    atomicAdd(&g_cnt[d3], 1);
}

// GEMM1 (391 tc tiles) + hist (independent) in ONE grid
__global__ __launch_bounds__(256) void kMain(
    const float* __restrict__ x, const float* __restrict__ W1,
    const float* __restrict__ as, const float* __restrict__ ad,
    const void* __restrict__ ei)
{
    __shared__ __half sm[128 * APAD + 32 * BPAD];
    if (blockIdx.x < GEMM1_TILES) gemm1_tc(blockIdx.x, sm, x, W1, as, ad);
    else                          hist_block(blockIdx.x - GEMM1_TILES, ei);
}

// ---------------- single-pass scan (unordered segment placement) -------------
__global__ void scan_kernel() {
    __shared__ int sh[2][256];
    __shared__ int base;
    int tid = threadIdx.x;
    int i = blockIdx.x * 256 + tid;
    int v = (i < N_NODES) ? g_cnt[i] : 0;
    sh[0][tid] = v;
    __syncthreads();
    int cur = 0;
#pragma unroll
    for (int s = 1; s < 256; s <<= 1) {
        int nxt = cur ^ 1;
        int t = sh[cur][tid];
        if (tid >= s) t += sh[cur][tid - s];
        sh[nxt][tid] = t;
        cur = nxt;
        __syncthreads();
    }
    int incl = sh[cur][tid];
    if (tid == 255) base = atomicAdd(&g_total, incl);
    __syncthreads();
    if (i < N_NODES) {
        int st = base + incl - v;
        g_start[i]  = st;
        g_cursor[i] = st;
    }
}

__global__ void scatter_kernel(const void* __restrict__ eiv) {
    int e0 = (blockIdx.x * 256 + threadIdx.x) * 4;
    if (e0 >= N_EDGES) return;
    int s0, s1, s2, s3, d0, d1, d2, d3;
    if (!g_idx_bad) {
        const longlong2* ps = (const longlong2*)((const long long*)eiv + e0);
        const longlong2* pd = (const longlong2*)((const long long*)eiv + N_EDGES + e0);
        longlong2 a = __ldg(ps), c = __ldg(ps + 1);
        longlong2 e = __ldg(pd), f = __ldg(pd + 1);
        s0 = (int)a.x; s1 = (int)a.y; s2 = (int)c.x; s3 = (int)c.y;
        d0 = (int)e.x; d1 = (int)e.y; d2 = (int)f.x; d3 = (int)f.y;
    } else {
        int4 a = __ldg((const int4*)((const int*)eiv + e0));
        int4 e = __ldg((const int4*)((const int*)eiv + N_EDGES + e0));
        s0 = a.x; s1 = a.y; s2 = a.z; s3 = a.w;
        d0 = e.x; d1 = e.y; d2 = e.z; d3 = e.w;
    }
    g_ssrc[atomicAdd(&g_cursor[d0], 1)] = s0;
    g_ssrc[atomicAdd(&g_cursor[d1], 1)] = s1;
    g_ssrc[atomicAdd(&g_cursor[d2], 1)] = s2;
    g_ssrc[atomicAdd(&g_cursor[d3], 1)] = s3;
}

// ---------------- layer-1 aggregation: fp16 rows, fp32 accumulate ------------
__global__ __launch_bounds__(256) void agg1_kernel(const float* __restrict__ b1) {
    __shared__ float sx[8][4][32];
    __shared__ int   ss[8][32];
    int wid = threadIdx.x >> 5;
    int gt = blockIdx.x * blockDim.x + threadIdx.x;
    if (gt == 0) g_idx_bad = 0;          // restore invariant
    int n = gt >> 5;
    if (n >= N_NODES) return;
    int lane = threadIdx.x & 31;
    int head = lane >> 3;
    int s0 = g_start[n];
    int c  = g_cnt[n];
    float4 adv = *(const float4*)(g_ad1 + n * 4);

    float a0=0,a1=0,a2=0,a3=0,a4=0,a5=0,a6=0,a7=0, denom=0.f;

    for (int base = 0; base < c; base += 32) {
        int m = min(32, c - base);
        if (lane < m) {
            int s = __ldg(g_ssrc + s0 + base + lane);
            float4 av = __ldg((const float4*)(g_as1 + s * 4));
            ss[wid][lane]    = s;
            sx[wid][0][lane] = __expf(lrelu(av.x + adv.x));
            sx[wid][1][lane] = __expf(lrelu(av.y + adv.y));
            sx[wid][2][lane] = __expf(lrelu(av.z + adv.z));
            sx[wid][3][lane] = __expf(lrelu(av.w + adv.w));
        }
        __syncwarp();
#pragma unroll 2
        for (int j = 0; j < m; j++) {
            int   s  = ss[wid][j];
            float xh = sx[wid][head][j];
            uint4 u = __ldg((const uint4*)(g_h1h + (size_t)s * L1_OUT + (lane << 3)));
            float2 f0 = __half22float2(*(__half2*)&u.x);
            float2 f1 = __half22float2(*(((__half2*)&u.x) + 1));
            float2 f2 = __half22float2(*(__half2*)&u.z);
            float2 f3 = __half22float2(*(((__half2*)&u.z) + 1));
            denom += xh;
            a0 = fmaf(xh, f0.x, a0); a1 = fmaf(xh, f0.y, a1);
            a2 = fmaf(xh, f1.x, a2); a3 = fmaf(xh, f1.y, a3);
            a4 = fmaf(xh, f2.x, a4); a5 = fmaf(xh, f2.y, a5);
            a6 = fmaf(xh, f3.x, a6); a7 = fmaf(xh, f3.y, a7);
        }
        __syncwarp();
    }

    float inv = 1.0f / (denom + EPS);
    int col = lane * 8;
    float4 bA = *(const float4*)(b1 + col);
    float4 bB = *(const float4*)(b1 + col + 4);
    __half2 o[4];
    o[0] = __floats2half2_rn(fmaxf(0.f, fmaf(a0, inv, bA.x)), fmaxf(0.f, fmaf(a1, inv, bA.y)));
    o[1] = __floats2half2_rn(fmaxf(0.f, fmaf(a2, inv, bA.z)), fmaxf(0.f, fmaf(a3, inv, bA.w)));
    o[2] = __floats2half2_rn(fmaxf(0.f, fmaf(a4, inv, bB.x)), fmaxf(0.f, fmaf(a5, inv, bB.y)));
    o[3] = __floats2half2_rn(fmaxf(0.f, fmaf(a6, inv, bB.z)), fmaxf(0.f, fmaf(a7, inv, bB.w)));
    *(uint4*)(g_out1h + (size_t)n * L1_OUT + col) = *(uint4*)o;
}

// ---------------- GEMM2 (fp16 A input) fused with alpha2 ---------------------
__global__ __launch_bounds__(256) void gemm2_kernel(
    const float* __restrict__ W2,
    const float* __restrict__ a_src, const float* __restrict__ a_dst)
{
    __shared__ float As[32][128];
    __shared__ float Bs[32][40];
    int tid = threadIdx.x;
    int tr = tid >> 3, tc = tid & 7;
    int bm = blockIdx.x * 128;

    int arow = tid >> 1;
    int acol = (tid & 1) * 16;
    const __half* Aptr = g_out1h + (size_t)(bm + arow) * L1_OUT + acol;
    bool aval = (bm + arow) < N_NODES;
    int bidx = tid * 5;

    uint4 sa0, sa1;
    float sb[5];
    uint4 zz = make_uint4(0, 0, 0, 0);
    sa0 = aval ? __ldg((const uint4*)Aptr)       : zz;
    sa1 = aval ? __ldg((const uint4*)Aptr + 1)   : zz;
#pragma unroll
    for (int j = 0; j < 5; j++) sb[j] = __ldg(W2 + bidx + j);

    float acc[4][5] = {};

    for (int kk = 0; kk < L1_OUT / 32; kk++) {
        __syncthreads();
        {
            const __half2* h0 = (const __half2*)&sa0;
            const __half2* h1 = (const __half2*)&sa1;
#pragma unroll
            for (int q = 0; q < 4; q++) {
                float2 f = __half22float2(h0[q]);
                As[acol + q * 2 + 0][arow] = f.x;
                As[acol + q * 2 + 1][arow] = f.y;
                float2 g = __half22float2(h1[q]);
                As[acol + 8 + q * 2 + 0][arow] = g.x;
                As[acol + 8 + q * 2 + 1][arow] = g.y;
            }
        }
#pragma unroll
        for (int j = 0; j < 5; j++) ((float*)Bs)[bidx + j] = sb[j];
        __syncthreads();
        if (kk < L1_OUT / 32 - 1) {
            int k0 = (kk + 1) * 32;
            sa0 = aval ? __ldg((const uint4*)(Aptr + k0))     : zz;
            sa1 = aval ? __ldg((const uint4*)(Aptr + k0) + 1) : zz;
#pragma unroll
            for (int j = 0; j < 5; j++) sb[j] = __ldg(W2 + k0 * CLASSES + bidx + j);
        }
#pragma unroll
        for (int k = 0; k < 32; k++) {
            float4 av = *(const float4*)&As[k][tr * 4];
            float a[4] = {av.x, av.y, av.z, av.w};
            float b[5];
#pragma unroll
            for (int j = 0; j < 5; j++) b[j] = Bs[k][tc * 5 + j];
#pragma unroll
            for (int x = 0; x < 4; x++)
#pragma unroll
                for (int y = 0; y < 5; y++)
                    acc[x][y] = fmaf(a[x], b[y], acc[x][y]);
        }
    }

    float asv[5], adv[5];
#pragma unroll
    for (int y = 0; y < 5; y++) {
        asv[y] = __ldg(a_src + tc * 5 + y);
        adv[y] = __ldg(a_dst + tc * 5 + y);
    }
    float ps[4], pd[4];
#pragma unroll
    for (int x = 0; x < 4; x++) {
        float s = 0.f, d = 0.f;
#pragma unroll
        for (int y = 0; y < 5; y++) {
            s = fmaf(acc[x][y], asv[y], s);
            d = fmaf(acc[x][y], adv[y], d);
        }
        ps[x] = s; pd[x] = d;
    }
#pragma unroll
    for (int s = 1; s < 8; s <<= 1) {
#pragma unroll
        for (int x = 0; x < 4; x++) {
            ps[x] += __shfl_xor_sync(0xffffffffu, ps[x], s);
            pd[x] += __shfl_xor_sync(0xffffffffu, pd[x], s);
        }
    }
#pragma unroll
    for (int x = 0; x < 4; x++) {
        int r = bm + tr * 4 + x;
        if (r < N_NODES) {
            __half* cp = g_h2h + (size_t)r * CLASSES + tc * 5;
#pragma unroll
            for (int y = 0; y < 5; y++) cp[y] = __float2half_rn(acc[x][y]);
            if (tc == 0) {
                g_as2[r] = ps[x];
                g_ad2[r] = pd[x];
            }
        }
    }
}

// ---------------- layer-2 aggregation + fused log_softmax (fp16 h2) ---------
__global__ __launch_bounds__(256) void agg2_kernel(const float* __restrict__ b2,
                                                   float* __restrict__ out) {
    __shared__ float sx[8][32];
    __shared__ int   ss[8][32];
    int wid = threadIdx.x >> 5;
    int n = (blockIdx.x * blockDim.x + threadIdx.x) >> 5;
    if (n >= N_NODES) return;
    int lane = threadIdx.x & 31;
    bool act = lane < 20;                 // lane covers cols 2l, 2l+1
    int s0 = g_start[n];
    int c  = g_cnt[n];
    float adn = __ldg(g_ad2 + n);

    float acc0 = 0.f, acc1 = 0.f, denom = 0.f;
    for (int base = 0; base < c; base += 32) {
        int m = min(32, c - base);
        if (lane < m) {
            int s = __ldg(g_ssrc + s0 + base + lane);
            float e = __ldg(g_as2 + s);
            ss[wid][lane] = s;
            sx[wid][lane] = __expf(lrelu(e + adn));
        }
        __syncwarp();
#pragma unroll 2
        for (int j = 0; j < m; j++) {
            int   s = ss[wid][j];
            float x = sx[wid][j];
            denom += x;
            if (act) {
                __half2 h = __ldg((const __half2*)(g_h2h + (size_t)s * CLASSES + 2 * lane));
                float2 f = __half22float2(h);
                acc0 = fmaf(x, f.x, acc0);
                acc1 = fmaf(x, f.y, acc1);
            }
        }
        __syncwarp();
    }
    float inv = 1.0f / (denom + EPS);
    float o0 = act ? fmaf(acc0, inv, __ldg(b2 + 2 * lane))     : -1e30f;
    float o1 = act ? fmaf(acc1, inv, __ldg(b2 + 2 * lane + 1)) : -1e30f;

    float mx = warpMax(fmaxf(o0, o1));
    float se = act ? (__expf(o0 - mx) + __expf(o1 - mx)) : 0.f;
    se = warpSum(se);
    float ls = __logf(se);
    if (act) {
        out[(size_t)n * CLASSES + 2 * lane]     = o0 - mx - ls;
        out[(size_t)n * CLASSES + 2 * lane + 1] = o1 - mx - ls;
    }
}

// ---------------- launch -----------------------------------------------------
extern "C" void kernel_launch(void* const* d_in, const int* in_sizes, int n_in,
                              void* d_out, int out_size) {
    const float* x    = (const float*)d_in[0];
    const void*  ei   = d_in[1];
    const float* W1   = (const float*)d_in[2];
    const float* asr1 = (const float*)d_in[3];
    const float* adt1 = (const float*)d_in[4];
    const float* b1   = (const float*)d_in[5];
    const float* W2   = (const float*)d_in[6];
    const float* asr2 = (const float*)d_in[7];
    const float* adt2 = (const float*)d_in[8];
    const float* b2   = (const float*)d_in[9];
    float* out = (float*)d_out;

    prep_kernel<<<(N_EDGES + 255) / 256, 256>>>((const long long*)ei);

    // GEMM1 (tensor cores) + hist fused in one grid
    kMain<<<GEMM1_TILES + EDGE_BLOCKS, 256>>>(x, W1, asr1, adt1, ei);

    scan_kernel<<<SCAN_BLOCKS, 256>>>();
    scatter_kernel<<<EDGE_BLOCKS, 256>>>(ei);

    agg1_kernel<<<(N_NODES + 7) / 8, 256>>>(b1);
    gemm2_kernel<<<(N_NODES + 127) / 128, 256>>>(W2, asr2, adt2);
    agg2_kernel<<<(N_NODES + 7) / 8, 256>>>(b2, out);
}

// round 7
// speedup vs baseline: 2.1010x; 1.2589x over previous
#include <cuda_runtime.h>
#include <cuda_fp16.h>
#include <cstdint>

#define N_NODES 50000
#define N_EDGES 800000
#define F_IN    128
#define HID     64
#define HEADS   4
#define L1_OUT  (HEADS*HID)   // 256
#define CLASSES 40
#define NEG_SLOPE 0.2f
#define EPS 1e-16f

#define GEMM1_TILES 391            // ceil(50000/128)
#define EDGE_BLOCKS 782            // ceil(800000 / (256*4))
#define SCAT_BLOCKS 1563           // ceil(800000 / (256*2))
#define SCAN_BLOCKS 196            // ceil(50000/256)

// ---------------- scratch --------------------------------------------------
__device__ __align__(16) __half g_h1h [(size_t)N_NODES * L1_OUT];
__device__ __align__(16) __half g_out1h[(size_t)N_NODES * L1_OUT];
__device__ __align__(16) __half g_h2h [(size_t)N_NODES * CLASSES];
__device__ __align__(16) float g_as1[N_NODES * HEADS];
__device__ __align__(16) float g_ad1[N_NODES * HEADS];
__device__ float g_as2[N_NODES];
__device__ float g_ad2[N_NODES];
__device__ int   g_cnt[N_NODES];
__device__ int   g_start[N_NODES];
__device__ int   g_cursor[N_NODES];
__device__ int   g_ssrc[N_EDGES];
__device__ int   g_idx_bad;        // 0 between launches; set by prep, reset by agg1
__device__ int   g_total;          // scan offset accumulator

// ---------------- helpers ---------------------------------------------------
__device__ __forceinline__ float warpMax(float v) {
#pragma unroll
    for (int s = 16; s > 0; s >>= 1)
        v = fmaxf(v, __shfl_xor_sync(0xffffffffu, v, s));
    return v;
}
__device__ __forceinline__ float warpSum(float v) {
#pragma unroll
    for (int s = 16; s > 0; s >>= 1)
        v += __shfl_xor_sync(0xffffffffu, v, s);
    return v;
}
__device__ __forceinline__ float lrelu(float x) {
    return (x > 0.f) ? x : NEG_SLOPE * x;
}
__device__ __forceinline__ uint32_t smem_u32(const void* p) {
    return (uint32_t)__cvta_generic_to_shared(p);
}
__device__ __forceinline__ void ldmatrix_x4(uint32_t* r, uint32_t addr) {
    asm volatile("ldmatrix.sync.aligned.m8n8.x4.shared.b16 {%0,%1,%2,%3}, [%4];"
                 : "=r"(r[0]), "=r"(r[1]), "=r"(r[2]), "=r"(r[3]) : "r"(addr));
}
__device__ __forceinline__ void ldmatrix_x4_trans(uint32_t* r, uint32_t addr) {
    asm volatile("ldmatrix.sync.aligned.m8n8.x4.trans.shared.b16 {%0,%1,%2,%3}, [%4];"
                 : "=r"(r[0]), "=r"(r[1]), "=r"(r[2]), "=r"(r[3]) : "r"(addr));
}
__device__ __forceinline__ void ldmatrix_x2_trans(uint32_t* r, uint32_t addr) {
    asm volatile("ldmatrix.sync.aligned.m8n8.x2.trans.shared.b16 {%0,%1}, [%2];"
                 : "=r"(r[0]), "=r"(r[1]) : "r"(addr));
}
__device__ __forceinline__ void mma16816(float* c, const uint32_t* a, const uint32_t* b) {
    asm volatile(
        "mma.sync.aligned.m16n8k16.row.col.f32.f16.f16.f32 "
        "{%0,%1,%2,%3}, {%4,%5,%6,%7}, {%8,%9}, {%0,%1,%2,%3};"
        : "+f"(c[0]), "+f"(c[1]), "+f"(c[2]), "+f"(c[3])
        : "r"(a[0]), "r"(a[1]), "r"(a[2]), "r"(a[3]), "r"(b[0]), "r"(b[1]));
}

// ---------------- prep: zero hist + dtype detection + total reset ------------
__global__ void prep_kernel(const long long* __restrict__ ei) {
    int i = blockIdx.x * blockDim.x + threadIdx.x;
    if (i == 0) g_total = 0;
    if (i < N_NODES) g_cnt[i] = 0;
    if (i < N_EDGES) {
        long long v = ei[i];
        if (v < 0 || v >= N_NODES) g_idx_bad = 1;
    }
}

// ---------------- GEMM1 via HMMA (unchanged from R6) -------------------------
#define APAD 40
#define BPAD 264
__device__ __forceinline__ void gemm1_tc(
    int unit, __half* smem,
    const float* __restrict__ A, const float* __restrict__ B,
    const float* __restrict__ a_src, const float* __restrict__ a_dst)
{
    __half* As = smem;                 // [128][APAD]
    __half* Bs = smem + 128 * APAD;    // [32][BPAD]
    const int tid = threadIdx.x;
    const int wid = tid >> 5, lane = tid & 31;
    const int bm = unit * 128;
    const int wm = (wid >> 2) * 64;
    const int wn = (wid & 3) * 64;
    const int head = wid & 3;

    const int ar = tid >> 1;
    const int ac = (tid & 1) * 16;
    const int br = tid >> 3;
    const int bc = (tid & 7) * 32;

    const float* Ap = A + (size_t)(bm + ar) * F_IN + ac;
    const bool aval = (bm + ar) < N_NODES;
    const float* Bp = B + (size_t)br * L1_OUT + bc;
    const float4 z = make_float4(0.f, 0.f, 0.f, 0.f);

    float acc[4][8][4];
#pragma unroll
    for (int i = 0; i < 4; i++)
#pragma unroll
        for (int j = 0; j < 8; j++)
#pragma unroll
            for (int q = 0; q < 4; q++) acc[i][j][q] = 0.f;

    float4 ra[4], rb[8];
#pragma unroll
    for (int q = 0; q < 4; q++) ra[q] = aval ? __ldg((const float4*)(Ap + q * 4)) : z;
#pragma unroll
    for (int q = 0; q < 8; q++) rb[q] = __ldg((const float4*)(Bp + q * 4));

    uint32_t a_addr[4], b_addr[4];
#pragma unroll
    for (int mi = 0; mi < 4; mi++)
        a_addr[mi] = smem_u32(As + (wm + mi * 16 + (lane & 15)) * APAD + (lane >> 4) * 8);
#pragma unroll
    for (int nj = 0; nj < 4; nj++)
        b_addr[nj] = smem_u32(Bs + (lane & 15) * BPAD + wn + nj * 16 + (lane >> 4) * 8);

    for (int kk = 0; kk < F_IN / 32; kk++) {
        if (kk > 0) __syncthreads();
        {
            __half2* Arow = (__half2*)(As + ar * APAD + ac);
#pragma unroll
            for (int q = 0; q < 4; q++) {
                Arow[q * 2]     = __floats2half2_rn(ra[q].x, ra[q].y);
                Arow[q * 2 + 1] = __floats2half2_rn(ra[q].z, ra[q].w);
            }
            __half2* Brow = (__half2*)(Bs + br * BPAD + bc);
#pragma unroll
            for (int q = 0; q < 8; q++) {
                Brow[q * 2]     = __floats2half2_rn(rb[q].x, rb[q].y);
                Brow[q * 2 + 1] = __floats2half2_rn(rb[q].z, rb[q].w);
            }
        }
        __syncthreads();
        if (kk < F_IN / 32 - 1) {
            int k0 = (kk + 1) * 32;
#pragma unroll
            for (int q = 0; q < 4; q++)
                ra[q] = aval ? __ldg((const float4*)(Ap + k0 + q * 4)) : z;
#pragma unroll
            for (int q = 0; q < 8; q++)
                rb[q] = __ldg((const float4*)(Bp + (size_t)k0 * L1_OUT + q * 4));
        }
#pragma unroll
        for (int k16 = 0; k16 < 2; k16++) {
            uint32_t af[4][4], bf[8][2];
#pragma unroll
            for (int mi = 0; mi < 4; mi++)
                ldmatrix_x4(af[mi], a_addr[mi] + k16 * 32);
#pragma unroll
            for (int nj = 0; nj < 4; nj++) {
                uint32_t t[4];
                ldmatrix_x4_trans(t, b_addr[nj] + k16 * 16 * BPAD * 2);
                bf[nj * 2][0] = t[0]; bf[nj * 2][1] = t[1];
                bf[nj * 2 + 1][0] = t[2]; bf[nj * 2 + 1][1] = t[3];
            }
#pragma unroll
            for (int mi = 0; mi < 4; mi++)
#pragma unroll
                for (int ni = 0; ni < 8; ni++)
                    mma16816(acc[mi][ni], af[mi], bf[ni]);
        }
    }

    float as0[8], as1[8], ad0[8], ad1[8];
    int cb = (lane & 3) * 2;
#pragma unroll
    for (int ni = 0; ni < 8; ni++) {
        int col = wn + ni * 8 + cb;
        as0[ni] = __ldg(a_src + col); as1[ni] = __ldg(a_src + col + 1);
        ad0[ni] = __ldg(a_dst + col); ad1[ni] = __ldg(a_dst + col + 1);
    }
#pragma unroll
    for (int mi = 0; mi < 4; mi++) {
        float sl = 0.f, sh = 0.f, dl = 0.f, dh = 0.f;
#pragma unroll
        for (int ni = 0; ni < 8; ni++) {
            sl = fmaf(acc[mi][ni][0], as0[ni], fmaf(acc[mi][ni][1], as1[ni], sl));
            sh = fmaf(acc[mi][ni][2], as0[ni], fmaf(acc[mi][ni][3], as1[ni], sh));
            dl = fmaf(acc[mi][ni][0], ad0[ni], fmaf(acc[mi][ni][1], ad1[ni], dl));
            dh = fmaf(acc[mi][ni][2], ad0[ni], fmaf(acc[mi][ni][3], ad1[ni], dh));
        }
#pragma unroll
        for (int s = 1; s < 4; s <<= 1) {
            sl += __shfl_xor_sync(0xffffffffu, sl, s);
            sh += __shfl_xor_sync(0xffffffffu, sh, s);
            dl += __shfl_xor_sync(0xffffffffu, dl, s);
            dh += __shfl_xor_sync(0xffffffffu, dh, s);
        }
        int row_lo = bm + wm + mi * 16 + (lane >> 2);
        int row_hi = row_lo + 8;
        if ((lane & 3) == 0) {
            if (row_lo < N_NODES) { g_as1[row_lo * 4 + head] = sl; g_ad1[row_lo * 4 + head] = dl; }
            if (row_hi < N_NODES) { g_as1[row_hi * 4 + head] = sh; g_ad1[row_hi * 4 + head] = dh; }
        }
        if (row_lo < N_NODES) {
            __half* p = g_h1h + (size_t)row_lo * L1_OUT + wn + cb;
#pragma unroll
            for (int ni = 0; ni < 8; ni++)
                *(__half2*)(p + ni * 8) = __floats2half2_rn(acc[mi][ni][0], acc[mi][ni][1]);
        }
        if (row_hi < N_NODES) {
            __half* p = g_h1h + (size_t)row_hi * L1_OUT + wn + cb;
#pragma unroll
            for (int ni = 0; ni < 8; ni++)
                *(__half2*)(p + ni * 8) = __floats2half2_rn(acc[mi][ni][2], acc[mi][ni][3]);
        }
    }
}

__device__ __forceinline__ void hist_block(int b, const void* __restrict__ eiv) {
    int e0 = (b * 256 + threadIdx.x) * 4;
    if (e0 >= N_EDGES) return;
    int d0, d1, d2, d3;
    if (!g_idx_bad) {
        const longlong2* p = (const longlong2*)((const long long*)eiv + N_EDGES + e0);
        longlong2 a = __ldg(p), c = __ldg(p + 1);
        d0 = (int)a.x; d1 = (int)a.y; d2 = (int)c.x; d3 = (int)c.y;
    } else {
        int4 a = __ldg((const int4*)((const int*)eiv + N_EDGES + e0));
        d0 = a.x; d1 = a.y; d2 = a.z; d3 = a.w;
    }
    atomicAdd(&g_cnt[d0], 1);
    atomicAdd(&g_cnt[d1], 1);
    atomicAdd(&g_cnt[d2], 1);
    atomicAdd(&g_cnt[d3], 1);
}

__global__ __launch_bounds__(256) void kMain(
    const float* __restrict__ x, const float* __restrict__ W1,
    const float* __restrict__ as, const float* __restrict__ ad,
    const void* __restrict__ ei)
{
    __shared__ __half sm[128 * APAD + 32 * BPAD];
    if (blockIdx.x < GEMM1_TILES) gemm1_tc(blockIdx.x, sm, x, W1, as, ad);
    else                          hist_block(blockIdx.x - GEMM1_TILES, ei);
}

// ---------------- single-pass scan (unordered segment placement) -------------
__global__ void scan_kernel() {
    __shared__ int sh[2][256];
    __shared__ int base;
    int tid = threadIdx.x;
    int i = blockIdx.x * 256 + tid;
    int v = (i < N_NODES) ? g_cnt[i] : 0;
    sh[0][tid] = v;
    __syncthreads();
    int cur = 0;
#pragma unroll
    for (int s = 1; s < 256; s <<= 1) {
        int nxt = cur ^ 1;
        int t = sh[cur][tid];
        if (tid >= s) t += sh[cur][tid - s];
        sh[nxt][tid] = t;
        cur = nxt;
        __syncthreads();
    }
    int incl = sh[cur][tid];
    if (tid == 255) base = atomicAdd(&g_total, incl);
    __syncthreads();
    if (i < N_NODES) {
        int st = base + incl - v;
        g_start[i]  = st;
        g_cursor[i] = st;
    }
}

// ---------------- scatter: 2 edges/thread ------------------------------------
__global__ void scatter_kernel(const void* __restrict__ eiv) {
    int e0 = (blockIdx.x * 256 + threadIdx.x) * 2;
    if (e0 >= N_EDGES) return;
    int s0, s1, d0, d1;
    if (!g_idx_bad) {
        longlong2 a = __ldg((const longlong2*)((const long long*)eiv + e0));
        longlong2 d = __ldg((const longlong2*)((const long long*)eiv + N_EDGES + e0));
        s0 = (int)a.x; s1 = (int)a.y; d0 = (int)d.x; d1 = (int)d.y;
    } else {
        int2 a = __ldg((const int2*)((const int*)eiv + e0));
        int2 d = __ldg((const int2*)((const int*)eiv + N_EDGES + e0));
        s0 = a.x; s1 = a.y; d0 = d.x; d1 = d.y;
    }
    g_ssrc[atomicAdd(&g_cursor[d0], 1)] = s0;
    g_ssrc[atomicAdd(&g_cursor[d1], 1)] = s1;
}

// ---------------- layer-1 aggregation: fp16 rows, unroll-2 gather ------------
__global__ __launch_bounds__(256) void agg1_kernel(const float* __restrict__ b1) {
    __shared__ float sx[8][4][32];
    __shared__ int   ss[8][32];
    int wid = threadIdx.x >> 5;
    int gt = blockIdx.x * blockDim.x + threadIdx.x;
    if (gt == 0) g_idx_bad = 0;
    int n = gt >> 5;
    if (n >= N_NODES) return;
    int lane = threadIdx.x & 31;
    int head = lane >> 3;
    int s0 = g_start[n];
    int c  = g_cnt[n];
    float4 adv = *(const float4*)(g_ad1 + n * 4);

    float a0=0,a1=0,a2=0,a3=0,a4=0,a5=0,a6=0,a7=0, denom=0.f;

    for (int base = 0; base < c; base += 32) {
        int m = min(32, c - base);
        if (lane < m) {
            int s = __ldg(g_ssrc + s0 + base + lane);
            float4 av = __ldg((const float4*)(g_as1 + s * 4));
            ss[wid][lane]    = s;
            sx[wid][0][lane] = __expf(lrelu(av.x + adv.x));
            sx[wid][1][lane] = __expf(lrelu(av.y + adv.y));
            sx[wid][2][lane] = __expf(lrelu(av.z + adv.z));
            sx[wid][3][lane] = __expf(lrelu(av.w + adv.w));
        }
        __syncwarp();
        int j = 0;
        for (; j + 2 <= m; j += 2) {
            int   sA = ss[wid][j],        sB = ss[wid][j + 1];
            float xA = sx[wid][head][j],  xB = sx[wid][head][j + 1];
            uint4 uA = __ldg((const uint4*)(g_h1h + (size_t)sA * L1_OUT + (lane << 3)));
            uint4 uB = __ldg((const uint4*)(g_h1h + (size_t)sB * L1_OUT + (lane << 3)));
            float2 fA0 = __half22float2(*(__half2*)&uA.x);
            float2 fA1 = __half22float2(*(((__half2*)&uA.x) + 1));
            float2 fA2 = __half22float2(*(__half2*)&uA.z);
            float2 fA3 = __half22float2(*(((__half2*)&uA.z) + 1));
            float2 fB0 = __half22float2(*(__half2*)&uB.x);
            float2 fB1 = __half22float2(*(((__half2*)&uB.x) + 1));
            float2 fB2 = __half22float2(*(__half2*)&uB.z);
            float2 fB3 = __half22float2(*(((__half2*)&uB.z) + 1));
            denom += xA + xB;
            a0 = fmaf(xA, fA0.x, fmaf(xB, fB0.x, a0));
            a1 = fmaf(xA, fA0.y, fmaf(xB, fB0.y, a1));
            a2 = fmaf(xA, fA1.x, fmaf(xB, fB1.x, a2));
            a3 = fmaf(xA, fA1.y, fmaf(xB, fB1.y, a3));
            a4 = fmaf(xA, fA2.x, fmaf(xB, fB2.x, a4));
            a5 = fmaf(xA, fA2.y, fmaf(xB, fB2.y, a5));
            a6 = fmaf(xA, fA3.x, fmaf(xB, fB3.x, a6));
            a7 = fmaf(xA, fA3.y, fmaf(xB, fB3.y, a7));
        }
        if (j < m) {
            int   s  = ss[wid][j];
            float xh = sx[wid][head][j];
            uint4 u = __ldg((const uint4*)(g_h1h + (size_t)s * L1_OUT + (lane << 3)));
            float2 f0 = __half22float2(*(__half2*)&u.x);
            float2 f1 = __half22float2(*(((__half2*)&u.x) + 1));
            float2 f2 = __half22float2(*(__half2*)&u.z);
            float2 f3 = __half22float2(*(((__half2*)&u.z) + 1));
            denom += xh;
            a0 = fmaf(xh, f0.x, a0); a1 = fmaf(xh, f0.y, a1);
            a2 = fmaf(xh, f1.x, a2); a3 = fmaf(xh, f1.y, a3);
            a4 = fmaf(xh, f2.x, a4); a5 = fmaf(xh, f2.y, a5);
            a6 = fmaf(xh, f3.x, a6); a7 = fmaf(xh, f3.y, a7);
        }
        __syncwarp();
    }

    float inv = 1.0f / (denom + EPS);
    int col = lane * 8;
    float4 bA = *(const float4*)(b1 + col);
    float4 bB = *(const float4*)(b1 + col + 4);
    __half2 o[4];
    o[0] = __floats2half2_rn(fmaxf(0.f, fmaf(a0, inv, bA.x)), fmaxf(0.f, fmaf(a1, inv, bA.y)));
    o[1] = __floats2half2_rn(fmaxf(0.f, fmaf(a2, inv, bA.z)), fmaxf(0.f, fmaf(a3, inv, bA.w)));
    o[2] = __floats2half2_rn(fmaxf(0.f, fmaf(a4, inv, bB.x)), fmaxf(0.f, fmaf(a5, inv, bB.y)));
    o[3] = __floats2half2_rn(fmaxf(0.f, fmaf(a6, inv, bB.z)), fmaxf(0.f, fmaf(a7, inv, bB.w)));
    *(uint4*)(g_out1h + (size_t)n * L1_OUT + col) = *(uint4*)o;
}

// ---------------- GEMM2 via HMMA (fp16 A, W2->fp16 smem) + fused alpha2 ------
#define G2APAD 40
#define G2BPAD 56
__global__ __launch_bounds__(256) void gemm2_kernel(
    const float* __restrict__ W2,
    const float* __restrict__ a_src, const float* __restrict__ a_dst)
{
    __shared__ __half As[128 * G2APAD];        // [128][40], 32 cols used per stage
    __shared__ __half Bs[L1_OUT * G2BPAD];     // [256][56], 40 cols valid
    const int tid = threadIdx.x;
    const int wid = tid >> 5, lane = tid & 31;
    const int bm = blockIdx.x * 128;
    const int wm = wid * 16;

    // W2 -> fp16 smem (whole matrix, resident for the full K loop)
    for (int i = tid; i < L1_OUT * CLASSES; i += 256) {
        int r = i / CLASSES, cc = i - r * CLASSES;
        Bs[r * G2BPAD + cc] = __float2half_rn(__ldg(W2 + i));
    }

    const int ar = tid >> 1;
    const int ac = (tid & 1) * 16;
    const __half* Ap = g_out1h + (size_t)(bm + ar) * L1_OUT + ac;
    const bool aval = (bm + ar) < N_NODES;
    const uint4 zz = make_uint4(0, 0, 0, 0);

    uint4 ra0 = aval ? __ldg((const uint4*)Ap)       : zz;
    uint4 ra1 = aval ? __ldg((const uint4*)(Ap + 8)) : zz;

    float acc[5][4];
#pragma unroll
    for (int nt = 0; nt < 5; nt++)
#pragma unroll
        for (int q = 0; q < 4; q++) acc[nt][q] = 0.f;

    const uint32_t a_addr = smem_u32(As + (wm + (lane & 15)) * G2APAD + (lane >> 4) * 8);
    const uint32_t b_row  = smem_u32(Bs + (lane & 15) * G2BPAD);

    for (int kk = 0; kk < L1_OUT / 32; kk++) {
        __syncthreads();                          // first pass also fences Bs
        *(uint4*)(As + ar * G2APAD + ac)     = ra0;
        *(uint4*)(As + ar * G2APAD + ac + 8) = ra1;
        __syncthreads();
        if (kk < L1_OUT / 32 - 1) {
            const __half* p = Ap + (kk + 1) * 32;
            ra0 = aval ? __ldg((const uint4*)p)       : zz;
            ra1 = aval ? __ldg((const uint4*)(p + 8)) : zz;
        }
#pragma unroll
        for (int k16 = 0; k16 < 2; k16++) {
            uint32_t af[4];
            ldmatrix_x4(af, a_addr + k16 * 32);
            int k0 = kk * 32 + k16 * 16;
#pragma unroll
            for (int nt = 0; nt < 5; nt++) {
                uint32_t bf[2];
                ldmatrix_x2_trans(bf, b_row + (uint32_t)k0 * (G2BPAD * 2) + nt * 16);
                mma16816(acc[nt], af, bf);
            }
        }
    }

    // epilogue: fused alpha2 dots + fp16 h2 store
    const int cb = (lane & 3) * 2;
    float ps_lo = 0.f, ps_hi = 0.f, pd_lo = 0.f, pd_hi = 0.f;
#pragma unroll
    for (int nt = 0; nt < 5; nt++) {
        int col = nt * 8 + cb;
        float s0 = __ldg(a_src + col), s1 = __ldg(a_src + col + 1);
        float d0 = __ldg(a_dst + col), d1 = __ldg(a_dst + col + 1);
        ps_lo = fmaf(acc[nt][0], s0, fmaf(acc[nt][1], s1, ps_lo));
        ps_hi = fmaf(acc[nt][2], s0, fmaf(acc[nt][3], s1, ps_hi));
        pd_lo = fmaf(acc[nt][0], d0, fmaf(acc[nt][1], d1, pd_lo));
        pd_hi = fmaf(acc[nt][2], d0, fmaf(acc[nt][3], d1, pd_hi));
    }
#pragma unroll
    for (int s = 1; s < 4; s <<= 1) {
        ps_lo += __shfl_xor_sync(0xffffffffu, ps_lo, s);
        ps_hi += __shfl_xor_sync(0xffffffffu, ps_hi, s);
        pd_lo += __shfl_xor_sync(0xffffffffu, pd_lo, s);
        pd_hi += __shfl_xor_sync(0xffffffffu, pd_hi, s);
    }
    int row_lo = bm + wm + (lane >> 2);
    int row_hi = row_lo + 8;
    if ((lane & 3) == 0) {
        if (row_lo < N_NODES) { g_as2[row_lo] = ps_lo; g_ad2[row_lo] = pd_lo; }
        if (row_hi < N_NODES) { g_as2[row_hi] = ps_hi; g_ad2[row_hi] = pd_hi; }
    }
    if (row_lo < N_NODES) {
        __half* p = g_h2h + (size_t)row_lo * CLASSES + cb;
#pragma unroll
        for (int nt = 0; nt < 5; nt++)
            *(__half2*)(p + nt * 8) = __floats2half2_rn(acc[nt][0], acc[nt][1]);
    }
    if (row_hi < N_NODES) {
        __half* p = g_h2h + (size_t)row_hi * CLASSES + cb;
#pragma unroll
        for (int nt = 0; nt < 5; nt++)
            *(__half2*)(p + nt * 8) = __floats2half2_rn(acc[nt][2], acc[nt][3]);
    }
}

// ---------------- layer-2 aggregation + fused log_softmax (fp16 h2) ---------
__global__ __launch_bounds__(256) void agg2_kernel(const float* __restrict__ b2,
                                                   float* __restrict__ out) {
    __shared__ float sx[8][32];
    __shared__ int   ss[8][32];
    int wid = threadIdx.x >> 5;
    int n = (blockIdx.x * blockDim.x + threadIdx.x) >> 5;
    if (n >= N_NODES) return;
    int lane = threadIdx.x & 31;
    bool act = lane < 20;
    int s0 = g_start[n];
    int c  = g_cnt[n];
    float adn = __ldg(g_ad2 + n);

    float acc0 = 0.f, acc1 = 0.f, denom = 0.f;
    for (int base = 0; base < c; base += 32) {
        int m = min(32, c - base);
        if (lane < m) {
            int s = __ldg(g_ssrc + s0 + base + lane);
            float e = __ldg(g_as2 + s);
            ss[wid][lane] = s;
            sx[wid][lane] = __expf(lrelu(e + adn));
        }
        __syncwarp();
        int j = 0;
        for (; j + 2 <= m; j += 2) {
            int   sA = ss[wid][j],  sB = ss[wid][j + 1];
            float xA = sx[wid][j],  xB = sx[wid][j + 1];
            denom += xA + xB;
            if (act) {
                __half2 hA = __ldg((const __half2*)(g_h2h + (size_t)sA * CLASSES + 2 * lane));
                __half2 hB = __ldg((const __half2*)(g_h2h + (size_t)sB * CLASSES + 2 * lane));
                float2 fA = __half22float2(hA);
                float2 fB = __half22float2(hB);
                acc0 = fmaf(xA, fA.x, fmaf(xB, fB.x, acc0));
                acc1 = fmaf(xA, fA.y, fmaf(xB, fB.y, acc1));
            }
        }
        if (j < m) {
            int   s = ss[wid][j];
            float x = sx[wid][j];
            denom += x;
            if (act) {
                __half2 h = __ldg((const __half2*)(g_h2h + (size_t)s * CLASSES + 2 * lane));
                float2 f = __half22float2(h);
                acc0 = fmaf(x, f.x, acc0);
                acc1 = fmaf(x, f.y, acc1);
            }
        }
        __syncwarp();
    }
    float inv = 1.0f / (denom + EPS);
    float o0 = act ? fmaf(acc0, inv, __ldg(b2 + 2 * lane))     : -1e30f;
    float o1 = act ? fmaf(acc1, inv, __ldg(b2 + 2 * lane + 1)) : -1e30f;

    float mx = warpMax(fmaxf(o0, o1));
    float se = act ? (__expf(o0 - mx) + __expf(o1 - mx)) : 0.f;
    se = warpSum(se);
    float ls = __logf(se);
    if (act) {
        out[(size_t)n * CLASSES + 2 * lane]     = o0 - mx - ls;
        out[(size_t)n * CLASSES + 2 * lane + 1] = o1 - mx - ls;
    }
}

// ---------------- launch -----------------------------------------------------
extern "C" void kernel_launch(void* const* d_in, const int* in_sizes, int n_in,
                              void* d_out, int out_size) {
    const float* x    = (const float*)d_in[0];
    const void*  ei   = d_in[1];
    const float* W1   = (const float*)d_in[2];
    const float* asr1 = (const float*)d_in[3];
    const float* adt1 = (const float*)d_in[4];
    const float* b1   = (const float*)d_in[5];
    const float* W2   = (const float*)d_in[6];
    const float* asr2 = (const float*)d_in[7];
    const float* adt2 = (const float*)d_in[8];
    const float* b2   = (const float*)d_in[9];
    float* out = (float*)d_out;

    prep_kernel<<<(N_EDGES + 255) / 256, 256>>>((const long long*)ei);

    kMain<<<GEMM1_TILES + EDGE_BLOCKS, 256>>>(x, W1, asr1, adt1, ei);

    scan_kernel<<<SCAN_BLOCKS, 256>>>();
    scatter_kernel<<<SCAT_BLOCKS, 256>>>(ei);

    agg1_kernel<<<(N_NODES + 7) / 8, 256>>>(b1);
    gemm2_kernel<<<(N_NODES + 127) / 128, 256>>>(W2, asr2, adt2);
    agg2_kernel<<<(N_NODES + 7) / 8, 256>>>(b2, out);
}